// round 1
// baseline (speedup 1.0000x reference)
#include <cuda_runtime.h>

// ---------------------------------------------------------------------------
// Problem constants
// ---------------------------------------------------------------------------
#define BQ    4096      // batch
#define SRCM1 49        // encoder steps (SRC-1)
#define TGTQ  25        // decoder steps
#define RQ    1024      // rnn size
#define HQ    67        // human size (output dim)
#define IQ    82        // input size

// ---------------------------------------------------------------------------
// Scratch: single __device__ array, addressed by compile-time offsets that are
// passed to kernels as plain integers (no cudaGetSymbolAddress / host API at
// all inside kernel_launch -> trivially graph-capturable).
// ---------------------------------------------------------------------------
constexpr long long OFF_HCAT = 0;                                   // [BQ, 2R]  h1|h2
constexpr long long OFF_GI1  = OFF_HCAT + (long long)BQ * 2 * RQ;   // [BQ, 3R]
constexpr long long OFF_GH1  = OFF_GI1  + (long long)BQ * 3 * RQ;   // [BQ, 3R]
constexpr long long OFF_GI2  = OFF_GH1  + (long long)BQ * 3 * RQ;   // [BQ, 3R]
constexpr long long OFF_GH2  = OFF_GI2  + (long long)BQ * 3 * RQ;   // [BQ, 3R]
constexpr long long OFF_X    = OFF_GH2  + (long long)BQ * 3 * RQ;   // [BQ, IQ]
constexpr long long SCRATCH_TOTAL = OFF_X + (long long)BQ * IQ;

__device__ float g_scratch[SCRATCH_TOTAL];

// ---------------------------------------------------------------------------
// Generic GEMM:  C[M,N] = A[M,K] @ W[N,K]^T + bias[N]  (+ optional residual)
//   - A, C, res may live in g_scratch (offset >= 0) or be external pointers.
//   - W row-major [N, K] (torch weight layout), bias length N.
//   - Fast path when K % 16 == 0 (callers guarantee 16B alignment there);
//     guarded element-wise path otherwise (K=82 input GEMMs).
//   - N edge guarded (FC uses N=67). M is always a multiple of 128 here.
// ---------------------------------------------------------------------------
#define BM 128
#define BN 64
#define BKT 16
#define TM 8
#define TN 4

__global__ __launch_bounds__(256, 2)
void gemm_nt_kernel(const float* __restrict__ Aext, long long Aoff, int lda,
                    const float* __restrict__ W,
                    const float* __restrict__ bias,
                    long long Roff, int res_ld,
                    float* __restrict__ Cext, long long Coff, int ldc,
                    int N, int K)
{
    const float* A = (Aoff >= 0) ? (g_scratch + Aoff) : Aext;
    float*       C = (Coff >= 0) ? (g_scratch + Coff) : Cext;
    const float* res = (Roff >= 0) ? (g_scratch + Roff) : nullptr;

    __shared__ float As[BKT][BM + 4];
    __shared__ float Ws[BKT][BN + 4];

    const int tid = threadIdx.x;
    const int tx  = tid & 15;      // N-dim thread coord (0..15)
    const int ty  = tid >> 4;      // M-dim thread coord (0..15)
    const int bm  = blockIdx.y * BM;
    const int bn  = blockIdx.x * BN;

    const int lkq  = (tid & 3) * 4;   // k offset inside tile (0,4,8,12)
    const int lrow = tid >> 2;        // 0..63

    float acc[TM][TN];
#pragma unroll
    for (int i = 0; i < TM; i++)
#pragma unroll
        for (int j = 0; j < TN; j++) acc[i][j] = 0.0f;

    const int  ktiles = (K + BKT - 1) / BKT;
    const bool fast   = ((K & (BKT - 1)) == 0);

    for (int kt = 0; kt < ktiles; kt++) {
        const int k0 = kt * BKT;
        if (fast) {
            // A tile: 2 float4 per thread, transposed into As[k][m]
#pragma unroll
            for (int r = 0; r < 2; r++) {
                const int row = lrow + r * 64;
                const float4 v = *reinterpret_cast<const float4*>(
                    A + (size_t)(bm + row) * lda + k0 + lkq);
                As[lkq + 0][row] = v.x;
                As[lkq + 1][row] = v.y;
                As[lkq + 2][row] = v.z;
                As[lkq + 3][row] = v.w;
            }
            // W tile: 1 float4 per thread
            float4 wv = make_float4(0.f, 0.f, 0.f, 0.f);
            if (bn + lrow < N)
                wv = *reinterpret_cast<const float4*>(
                    W + (size_t)(bn + lrow) * K + k0 + lkq);
            Ws[lkq + 0][lrow] = wv.x;
            Ws[lkq + 1][lrow] = wv.y;
            Ws[lkq + 2][lrow] = wv.z;
            Ws[lkq + 3][lrow] = wv.w;
        } else {
#pragma unroll
            for (int r = 0; r < 2; r++) {
                const int row = lrow + r * 64;
#pragma unroll
                for (int j = 0; j < 4; j++) {
                    const int k = k0 + lkq + j;
                    As[lkq + j][row] =
                        (k < K) ? A[(size_t)(bm + row) * lda + k] : 0.0f;
                }
            }
#pragma unroll
            for (int j = 0; j < 4; j++) {
                const int k = k0 + lkq + j;
                Ws[lkq + j][lrow] =
                    (k < K && (bn + lrow) < N) ? W[(size_t)(bn + lrow) * K + k] : 0.0f;
            }
        }
        __syncthreads();

#pragma unroll
        for (int kk = 0; kk < BKT; kk++) {
            const float4 a0 = *reinterpret_cast<const float4*>(&As[kk][ty * TM]);
            const float4 a1 = *reinterpret_cast<const float4*>(&As[kk][ty * TM + 4]);
            const float4 bv = *reinterpret_cast<const float4*>(&Ws[kk][tx * TN]);
            const float av[TM] = {a0.x, a0.y, a0.z, a0.w, a1.x, a1.y, a1.z, a1.w};
            const float bw[TN] = {bv.x, bv.y, bv.z, bv.w};
#pragma unroll
            for (int i = 0; i < TM; i++)
#pragma unroll
                for (int j = 0; j < TN; j++)
                    acc[i][j] = fmaf(av[i], bw[j], acc[i][j]);
        }
        __syncthreads();
    }

    // Epilogue: bias (+ residual), guarded on N edge.
#pragma unroll
    for (int i = 0; i < TM; i++) {
        const int m = bm + ty * TM + i;
#pragma unroll
        for (int j = 0; j < TN; j++) {
            const int n = bn + tx * TN + j;
            if (n < N) {
                float v = acc[i][j] + bias[n];
                if (res) v += res[(size_t)m * res_ld + n];
                C[(size_t)m * ldc + n] = v;
            }
        }
    }
}

// ---------------------------------------------------------------------------
// GRU elementwise combine: h_new = (1-z)*n + z*h  with torch gate order (r,z,n)
//   gi/gh: [BQ, 3R] in scratch, h: strided region of hcat (stride 2R)
// ---------------------------------------------------------------------------
__global__ void gru_combine_kernel(long long gi_off, long long gh_off, long long h_off)
{
    const int idx = blockIdx.x * blockDim.x + threadIdx.x;
    if (idx >= BQ * RQ) return;
    const int b = idx >> 10;          // / RQ
    const int j = idx & (RQ - 1);     // % RQ

    const float* gi = g_scratch + gi_off;
    const float* gh = g_scratch + gh_off;
    float*       h  = g_scratch + h_off;

    const size_t g = (size_t)b * 3 * RQ + j;
    const float ir = gi[g], iz = gi[g + RQ], inn = gi[g + 2 * RQ];
    const float hr = gh[g], hz = gh[g + RQ], hn  = gh[g + 2 * RQ];

    const float r = 1.0f / (1.0f + expf(-(ir + hr)));
    const float z = 1.0f / (1.0f + expf(-(iz + hz)));
    const float n = tanhf(inn + r * hn);

    const size_t hi = (size_t)b * 2 * RQ + j;
    const float hp = h[hi];
    h[hi] = (1.0f - z) * n + z * hp;
}

// ---------------------------------------------------------------------------
// Decoder input assembly: x = concat(prev_output, dec_t[:, H:])
//   t == 0: x = dec[:, 0, :]   (prev0 == dec[0][:, :H])
// ---------------------------------------------------------------------------
__global__ void build_x_kernel(const float* __restrict__ dec,
                               const float* __restrict__ out, int t)
{
    const int idx = blockIdx.x * blockDim.x + threadIdx.x;
    if (idx >= BQ * IQ) return;
    const int b = idx / IQ;
    const int i = idx - b * IQ;
    float v;
    if (t == 0) {
        v = dec[(size_t)b * TGTQ * IQ + i];
    } else if (i < HQ) {
        v = out[(size_t)(b * TGTQ + (t - 1)) * HQ + i];
    } else {
        v = dec[(size_t)(b * TGTQ + t) * IQ + i];
    }
    g_scratch[OFF_X + idx] = v;
}

__global__ void zero_kernel(long long off, long long count)
{
    const long long idx = (long long)blockIdx.x * blockDim.x + threadIdx.x;
    if (idx < count) g_scratch[off + idx] = 0.0f;
}

// ---------------------------------------------------------------------------
// Launch: 421 kernel launches total, all on the default stream (graph-captured)
// ---------------------------------------------------------------------------
extern "C" void kernel_launch(void* const* d_in, const int* in_sizes, int n_in,
                              void* d_out, int out_size)
{
    const float* enc = (const float*)d_in[0];   // [B, 49, 82]
    const float* dec = (const float*)d_in[1];   // [B, 25, 82]
    const float* Wi1 = (const float*)d_in[2];   // [3R, I]
    const float* Wh1 = (const float*)d_in[3];   // [3R, R]
    const float* bi1 = (const float*)d_in[4];
    const float* bh1 = (const float*)d_in[5];
    const float* Wi2 = (const float*)d_in[6];   // [3R, R]
    const float* Wh2 = (const float*)d_in[7];   // [3R, R]
    const float* bi2 = (const float*)d_in[8];
    const float* bh2 = (const float*)d_in[9];
    const float* Wfc = (const float*)d_in[10];  // [H, 2R]
    const float* bfc = (const float*)d_in[11];
    float* out = (float*)d_out;                 // [B, 25, H]
    (void)in_sizes; (void)n_in; (void)out_size;

    const dim3 blk(256);
    const dim3 grid3R((3 * RQ) / BN, BQ / BM);          // (48, 32)
    const dim3 gridFC((HQ + BN - 1) / BN, BQ / BM);     // (2, 32)
    const int  combine_blocks = (BQ * RQ) / 256;        // 16384
    const int  bx_blocks = (BQ * IQ + 255) / 256;

    // h1 = h2 = 0
    zero_kernel<<<(int)((BQ * 2LL * RQ + 255) / 256), blk>>>(OFF_HCAT, (long long)BQ * 2 * RQ);

    // ---------------- encoder: 49 steps ----------------
    for (int t = 0; t < SRCM1; t++) {
        // gi1 = x @ Wi1^T + bi1   (x strided straight out of encoder_inputs)
        gemm_nt_kernel<<<grid3R, blk>>>(enc + (size_t)t * IQ, -1, SRCM1 * IQ,
                                        Wi1, bi1, -1, 0,
                                        nullptr, OFF_GI1, 3 * RQ, 3 * RQ, IQ);
        // gh1 = h1 @ Wh1^T + bh1
        gemm_nt_kernel<<<grid3R, blk>>>(nullptr, OFF_HCAT, 2 * RQ,
                                        Wh1, bh1, -1, 0,
                                        nullptr, OFF_GH1, 3 * RQ, 3 * RQ, RQ);
        gru_combine_kernel<<<combine_blocks, blk>>>(OFF_GI1, OFF_GH1, OFF_HCAT);

        // gi2 = s1 @ Wi2^T + bi2 ; gh2 = h2 @ Wh2^T + bh2
        gemm_nt_kernel<<<grid3R, blk>>>(nullptr, OFF_HCAT, 2 * RQ,
                                        Wi2, bi2, -1, 0,
                                        nullptr, OFF_GI2, 3 * RQ, 3 * RQ, RQ);
        gemm_nt_kernel<<<grid3R, blk>>>(nullptr, OFF_HCAT + RQ, 2 * RQ,
                                        Wh2, bh2, -1, 0,
                                        nullptr, OFF_GH2, 3 * RQ, 3 * RQ, RQ);
        gru_combine_kernel<<<combine_blocks, blk>>>(OFF_GI2, OFF_GH2, OFF_HCAT + RQ);
    }

    // ---------------- decoder: 25 steps ----------------
    for (int t = 0; t < TGTQ; t++) {
        build_x_kernel<<<bx_blocks, blk>>>(dec, out, t);

        gemm_nt_kernel<<<grid3R, blk>>>(nullptr, OFF_X, IQ,
                                        Wi1, bi1, -1, 0,
                                        nullptr, OFF_GI1, 3 * RQ, 3 * RQ, IQ);
        gemm_nt_kernel<<<grid3R, blk>>>(nullptr, OFF_HCAT, 2 * RQ,
                                        Wh1, bh1, -1, 0,
                                        nullptr, OFF_GH1, 3 * RQ, 3 * RQ, RQ);
        gru_combine_kernel<<<combine_blocks, blk>>>(OFF_GI1, OFF_GH1, OFF_HCAT);

        gemm_nt_kernel<<<grid3R, blk>>>(nullptr, OFF_HCAT, 2 * RQ,
                                        Wi2, bi2, -1, 0,
                                        nullptr, OFF_GI2, 3 * RQ, 3 * RQ, RQ);
        gemm_nt_kernel<<<grid3R, blk>>>(nullptr, OFF_HCAT + RQ, 2 * RQ,
                                        Wh2, bh2, -1, 0,
                                        nullptr, OFF_GH2, 3 * RQ, 3 * RQ, RQ);
        gru_combine_kernel<<<combine_blocks, blk>>>(OFF_GI2, OFF_GH2, OFF_HCAT + RQ);

        // out_t = x[:, :H] + [h1|h2] @ Wfc^T + bfc   (residual fused into GEMM)
        gemm_nt_kernel<<<gridFC, blk>>>(nullptr, OFF_HCAT, 2 * RQ,
                                        Wfc, bfc, OFF_X, IQ,
                                        out + (size_t)t * HQ, -1, TGTQ * HQ,
                                        HQ, 2 * RQ);
    }
}

// round 3
// speedup vs baseline: 2.6777x; 2.6777x over previous
#include <cuda_runtime.h>
#include <cuda_bf16.h>
#include <cstdint>

// ---------------------------------------------------------------------------
// Problem constants
// ---------------------------------------------------------------------------
#define BQ    4096      // batch
#define SRCM1 49        // encoder steps (SRC-1)
#define TGTQ  25        // decoder steps
#define RQ    1024      // rnn size
#define HQ    67        // human size (output dim)
#define IQ    82        // input size

// ---------------------------------------------------------------------------
// Scratch
// ---------------------------------------------------------------------------
constexpr long long OFF_HCAT = 0;                                   // [BQ, 2R]  h1|h2
constexpr long long OFF_GI1  = OFF_HCAT + (long long)BQ * 2 * RQ;   // [BQ, 3R]
constexpr long long OFF_GH1  = OFF_GI1  + (long long)BQ * 3 * RQ;   // [BQ, 3R]
constexpr long long OFF_GI2  = OFF_GH1  + (long long)BQ * 3 * RQ;   // [BQ, 3R]
constexpr long long OFF_GH2  = OFF_GI2  + (long long)BQ * 3 * RQ;   // [BQ, 3R]
constexpr long long OFF_X    = OFF_GH2  + (long long)BQ * 3 * RQ;   // [BQ, IQ]
constexpr long long SCRATCH_TOTAL = OFF_X + (long long)BQ * IQ;

__device__ float g_scratch[SCRATCH_TOTAL];

// ---------------------------------------------------------------------------
// bf16x3 split-precision tensor-core GEMM
//   C[M,N] = A[M,K] @ W[N,K]^T + bias[N] (+ optional residual)
//   Each fp32 operand split: hi = bf16(a), lo = bf16(a - hi).
//   a*b ~= a_lo*b_hi + a_hi*b_lo + a_hi*b_hi   (3 HMMA, fp32 accumulate)
//   -> effective operand eps ~2^-16, final rel_err ~1e-4 for this model.
//
//   Block tile 128x64x32, 256 threads, 8 warps, warp tile 32x32.
//   Smem: k-pair packed bf16x2 words, layout [k/2][m] with +8 pad
//   (row stride 136/72 -> conflict-free fragment LDS, 2-way on stores).
// ---------------------------------------------------------------------------
#define BM 128
#define BN 64
#define BK 32           // fp32 k-elements per tile (16 packed k2 rows)

__device__ __forceinline__ void split2(float x, float y, uint32_t& hi, uint32_t& lo)
{
    __nv_bfloat162 h = __floats2bfloat162_rn(x, y);       // low = x (even k)
    float xr = x - __bfloat162float(__low2bfloat16(h));
    float yr = y - __bfloat162float(__high2bfloat16(h));
    __nv_bfloat162 l = __floats2bfloat162_rn(xr, yr);
    hi = *reinterpret_cast<uint32_t*>(&h);
    lo = *reinterpret_cast<uint32_t*>(&l);
}

#define MMA_BF16(ACC, A0, A1, A2, A3, B0, B1)                                  \
    asm volatile(                                                              \
        "mma.sync.aligned.m16n8k16.row.col.f32.bf16.bf16.f32 "                 \
        "{%0,%1,%2,%3}, {%4,%5,%6,%7}, {%8,%9}, {%0,%1,%2,%3};"                \
        : "+f"((ACC)[0]), "+f"((ACC)[1]), "+f"((ACC)[2]), "+f"((ACC)[3])       \
        : "r"(A0), "r"(A1), "r"(A2), "r"(A3), "r"(B0), "r"(B1))

__global__ __launch_bounds__(256, 2)
void gemm_bf16x3_kernel(const float* __restrict__ Aext, long long Aoff, int lda,
                        const float* __restrict__ W,
                        const float* __restrict__ bias,
                        long long Roff, int res_ld,
                        float* __restrict__ Cext, long long Coff, int ldc,
                        int N, int K)
{
    const float* A = (Aoff >= 0) ? (g_scratch + Aoff) : Aext;
    float*       C = (Coff >= 0) ? (g_scratch + Coff) : Cext;
    const float* res = (Roff >= 0) ? (g_scratch + Roff) : nullptr;

    __shared__ uint32_t AsH[BK / 2][BM + 8];   // [k2][m], stride 136
    __shared__ uint32_t AsL[BK / 2][BM + 8];
    __shared__ uint32_t BsH[BK / 2][BN + 8];   // [k2][n], stride 72
    __shared__ uint32_t BsL[BK / 2][BN + 8];

    const int tid  = threadIdx.x;
    const int bm   = blockIdx.y * BM;
    const int bn   = blockIdx.x * BN;

    // A staging: row = tid>>1 (0..127), k half = (tid&1)*16 (16 fp32 each)
    const int arow = tid >> 1;
    const int akh  = (tid & 1) * 16;
    // W staging: row = tid>>2 (0..63), k quarter = (tid&3)*8 (8 fp32 each)
    const int wrow = tid >> 2;
    const int wkq  = (tid & 3) * 8;

    const int lane = tid & 31;
    const int warp = tid >> 5;
    const int wm   = (warp >> 1) * 32;    // warp M origin
    const int wn   = (warp & 1) * 32;     // warp N origin
    const int gid  = lane >> 2;           // 0..7
    const int tig  = lane & 3;            // 0..3

    const bool fast   = ((K & (BK - 1)) == 0) && ((lda & 3) == 0);
    const int  ktiles = (K + BK - 1) / BK;

    float acc[2][4][4];
#pragma unroll
    for (int mt = 0; mt < 2; mt++)
#pragma unroll
        for (int nt = 0; nt < 4; nt++)
#pragma unroll
            for (int q = 0; q < 4; q++) acc[mt][nt][q] = 0.0f;

    for (int kt = 0; kt < ktiles; kt++) {
        const int k0 = kt * BK;
        __syncthreads();   // previous compute done before overwriting smem

        // ---- stage A tile (with split) ----
        float av[16];
        if (fast) {
#pragma unroll
            for (int q = 0; q < 4; q++) {
                const float4 v = *reinterpret_cast<const float4*>(
                    A + (size_t)(bm + arow) * lda + k0 + akh + q * 4);
                av[q * 4 + 0] = v.x; av[q * 4 + 1] = v.y;
                av[q * 4 + 2] = v.z; av[q * 4 + 3] = v.w;
            }
        } else {
#pragma unroll
            for (int j = 0; j < 16; j++) {
                const int k = k0 + akh + j;
                av[j] = (k < K) ? A[(size_t)(bm + arow) * lda + k] : 0.0f;
            }
        }
#pragma unroll
        for (int j = 0; j < 8; j++) {
            uint32_t hi, lo;
            split2(av[2 * j], av[2 * j + 1], hi, lo);
            AsH[akh / 2 + j][arow] = hi;
            AsL[akh / 2 + j][arow] = lo;
        }

        // ---- stage W tile (with split) ----
        float wv[8];
        if (fast && (bn + wrow) < N) {
#pragma unroll
            for (int q = 0; q < 2; q++) {
                const float4 v = *reinterpret_cast<const float4*>(
                    W + (size_t)(bn + wrow) * K + k0 + wkq + q * 4);
                wv[q * 4 + 0] = v.x; wv[q * 4 + 1] = v.y;
                wv[q * 4 + 2] = v.z; wv[q * 4 + 3] = v.w;
            }
        } else {
#pragma unroll
            for (int j = 0; j < 8; j++) {
                const int k = k0 + wkq + j;
                wv[j] = (k < K && (bn + wrow) < N)
                    ? W[(size_t)(bn + wrow) * K + k] : 0.0f;
            }
        }
#pragma unroll
        for (int j = 0; j < 4; j++) {
            uint32_t hi, lo;
            split2(wv[2 * j], wv[2 * j + 1], hi, lo);
            BsH[wkq / 2 + j][wrow] = hi;
            BsL[wkq / 2 + j][wrow] = lo;
        }
        __syncthreads();

        // ---- compute: 2 k16-chunks ----
#pragma unroll
        for (int kc = 0; kc < 2; kc++) {
            const int kb = kc * 8;   // k2 base
            uint32_t afH[2][4], afL[2][4], bfH[4][2], bfL[4][2];
#pragma unroll
            for (int mt = 0; mt < 2; mt++) {
                const int r0 = wm + mt * 16 + gid;
                afH[mt][0] = AsH[kb + tig][r0];
                afH[mt][1] = AsH[kb + tig][r0 + 8];
                afH[mt][2] = AsH[kb + tig + 4][r0];
                afH[mt][3] = AsH[kb + tig + 4][r0 + 8];
                afL[mt][0] = AsL[kb + tig][r0];
                afL[mt][1] = AsL[kb + tig][r0 + 8];
                afL[mt][2] = AsL[kb + tig + 4][r0];
                afL[mt][3] = AsL[kb + tig + 4][r0 + 8];
            }
#pragma unroll
            for (int nt = 0; nt < 4; nt++) {
                const int c0 = wn + nt * 8 + gid;
                bfH[nt][0] = BsH[kb + tig][c0];
                bfH[nt][1] = BsH[kb + tig + 4][c0];
                bfL[nt][0] = BsL[kb + tig][c0];
                bfL[nt][1] = BsL[kb + tig + 4][c0];
            }
#pragma unroll
            for (int mt = 0; mt < 2; mt++)
#pragma unroll
                for (int nt = 0; nt < 4; nt++) {
                    // small terms first, then dominant hi*hi
                    MMA_BF16(acc[mt][nt],
                             afL[mt][0], afL[mt][1], afL[mt][2], afL[mt][3],
                             bfH[nt][0], bfH[nt][1]);
                    MMA_BF16(acc[mt][nt],
                             afH[mt][0], afH[mt][1], afH[mt][2], afH[mt][3],
                             bfL[nt][0], bfL[nt][1]);
                    MMA_BF16(acc[mt][nt],
                             afH[mt][0], afH[mt][1], afH[mt][2], afH[mt][3],
                             bfH[nt][0], bfH[nt][1]);
                }
        }
    }

    // ---- epilogue: bias (+ residual), N edge guarded ----
#pragma unroll
    for (int mt = 0; mt < 2; mt++) {
#pragma unroll
        for (int nt = 0; nt < 4; nt++) {
            const int m0 = bm + wm + mt * 16 + gid;
            const int n0 = bn + wn + nt * 8 + 2 * tig;
#pragma unroll
            for (int h = 0; h < 2; h++) {
                const int m = m0 + h * 8;
#pragma unroll
                for (int q = 0; q < 2; q++) {
                    const int n = n0 + q;
                    if (n < N) {
                        float v = acc[mt][nt][h * 2 + q] + bias[n];
                        if (res) v += res[(size_t)m * res_ld + n];
                        C[(size_t)m * ldc + n] = v;
                    }
                }
            }
        }
    }
}

// ---------------------------------------------------------------------------
// GRU elementwise combine: h_new = (1-z)*n + z*h  (torch gate order r,z,n)
// ---------------------------------------------------------------------------
__global__ void gru_combine_kernel(long long gi_off, long long gh_off, long long h_off)
{
    const int idx = blockIdx.x * blockDim.x + threadIdx.x;
    if (idx >= BQ * RQ) return;
    const int b = idx >> 10;
    const int j = idx & (RQ - 1);

    const float* gi = g_scratch + gi_off;
    const float* gh = g_scratch + gh_off;
    float*       h  = g_scratch + h_off;

    const size_t g = (size_t)b * 3 * RQ + j;
    const float ir = gi[g], iz = gi[g + RQ], inn = gi[g + 2 * RQ];
    const float hr = gh[g], hz = gh[g + RQ], hn  = gh[g + 2 * RQ];

    const float r = 1.0f / (1.0f + expf(-(ir + hr)));
    const float z = 1.0f / (1.0f + expf(-(iz + hz)));
    const float n = tanhf(inn + r * hn);

    const size_t hi = (size_t)b * 2 * RQ + j;
    const float hp = h[hi];
    h[hi] = (1.0f - z) * n + z * hp;
}

// ---------------------------------------------------------------------------
// Decoder input assembly: x = concat(prev_output, dec_t[:, H:]); t==0 -> dec[0]
// ---------------------------------------------------------------------------
__global__ void build_x_kernel(const float* __restrict__ dec,
                               const float* __restrict__ out, int t)
{
    const int idx = blockIdx.x * blockDim.x + threadIdx.x;
    if (idx >= BQ * IQ) return;
    const int b = idx / IQ;
    const int i = idx - b * IQ;
    float v;
    if (t == 0) {
        v = dec[(size_t)b * TGTQ * IQ + i];
    } else if (i < HQ) {
        v = out[(size_t)(b * TGTQ + (t - 1)) * HQ + i];
    } else {
        v = dec[(size_t)(b * TGTQ + t) * IQ + i];
    }
    g_scratch[OFF_X + idx] = v;
}

__global__ void zero_kernel(long long off, long long count)
{
    const long long idx = (long long)blockIdx.x * blockDim.x + threadIdx.x;
    if (idx < count) g_scratch[off + idx] = 0.0f;
}

// ---------------------------------------------------------------------------
// Launch
// ---------------------------------------------------------------------------
extern "C" void kernel_launch(void* const* d_in, const int* in_sizes, int n_in,
                              void* d_out, int out_size)
{
    const float* enc = (const float*)d_in[0];
    const float* dec = (const float*)d_in[1];
    const float* Wi1 = (const float*)d_in[2];
    const float* Wh1 = (const float*)d_in[3];
    const float* bi1 = (const float*)d_in[4];
    const float* bh1 = (const float*)d_in[5];
    const float* Wi2 = (const float*)d_in[6];
    const float* Wh2 = (const float*)d_in[7];
    const float* bi2 = (const float*)d_in[8];
    const float* bh2 = (const float*)d_in[9];
    const float* Wfc = (const float*)d_in[10];
    const float* bfc = (const float*)d_in[11];
    float* out = (float*)d_out;
    (void)in_sizes; (void)n_in; (void)out_size;

    const dim3 blk(256);
    const dim3 grid3R((3 * RQ) / BN, BQ / BM);          // (48, 32)
    const dim3 gridFC((HQ + BN - 1) / BN, BQ / BM);     // (2, 32)
    const int  combine_blocks = (BQ * RQ) / 256;
    const int  bx_blocks = (BQ * IQ + 255) / 256;

    zero_kernel<<<(int)((BQ * 2LL * RQ + 255) / 256), blk>>>(OFF_HCAT, (long long)BQ * 2 * RQ);

    // ---------------- encoder: 49 steps ----------------
    for (int t = 0; t < SRCM1; t++) {
        gemm_bf16x3_kernel<<<grid3R, blk>>>(enc + (size_t)t * IQ, -1, SRCM1 * IQ,
                                            Wi1, bi1, -1, 0,
                                            nullptr, OFF_GI1, 3 * RQ, 3 * RQ, IQ);
        gemm_bf16x3_kernel<<<grid3R, blk>>>(nullptr, OFF_HCAT, 2 * RQ,
                                            Wh1, bh1, -1, 0,
                                            nullptr, OFF_GH1, 3 * RQ, 3 * RQ, RQ);
        gru_combine_kernel<<<combine_blocks, blk>>>(OFF_GI1, OFF_GH1, OFF_HCAT);

        gemm_bf16x3_kernel<<<grid3R, blk>>>(nullptr, OFF_HCAT, 2 * RQ,
                                            Wi2, bi2, -1, 0,
                                            nullptr, OFF_GI2, 3 * RQ, 3 * RQ, RQ);
        gemm_bf16x3_kernel<<<grid3R, blk>>>(nullptr, OFF_HCAT + RQ, 2 * RQ,
                                            Wh2, bh2, -1, 0,
                                            nullptr, OFF_GH2, 3 * RQ, 3 * RQ, RQ);
        gru_combine_kernel<<<combine_blocks, blk>>>(OFF_GI2, OFF_GH2, OFF_HCAT + RQ);
    }

    // ---------------- decoder: 25 steps ----------------
    for (int t = 0; t < TGTQ; t++) {
        build_x_kernel<<<bx_blocks, blk>>>(dec, out, t);

        gemm_bf16x3_kernel<<<grid3R, blk>>>(nullptr, OFF_X, IQ,
                                            Wi1, bi1, -1, 0,
                                            nullptr, OFF_GI1, 3 * RQ, 3 * RQ, IQ);
        gemm_bf16x3_kernel<<<grid3R, blk>>>(nullptr, OFF_HCAT, 2 * RQ,
                                            Wh1, bh1, -1, 0,
                                            nullptr, OFF_GH1, 3 * RQ, 3 * RQ, RQ);
        gru_combine_kernel<<<combine_blocks, blk>>>(OFF_GI1, OFF_GH1, OFF_HCAT);

        gemm_bf16x3_kernel<<<grid3R, blk>>>(nullptr, OFF_HCAT, 2 * RQ,
                                            Wi2, bi2, -1, 0,
                                            nullptr, OFF_GI2, 3 * RQ, 3 * RQ, RQ);
        gemm_bf16x3_kernel<<<grid3R, blk>>>(nullptr, OFF_HCAT + RQ, 2 * RQ,
                                            Wh2, bh2, -1, 0,
                                            nullptr, OFF_GH2, 3 * RQ, 3 * RQ, RQ);
        gru_combine_kernel<<<combine_blocks, blk>>>(OFF_GI2, OFF_GH2, OFF_HCAT + RQ);

        gemm_bf16x3_kernel<<<gridFC, blk>>>(nullptr, OFF_HCAT, 2 * RQ,
                                            Wfc, bfc, OFF_X, IQ,
                                            out + (size_t)t * HQ, -1, TGTQ * HQ,
                                            HQ, 2 * RQ);
    }
}

// round 5
// speedup vs baseline: 2.8944x; 1.0809x over previous
#include <cuda_runtime.h>
#include <cuda_bf16.h>
#include <cstdint>

// ---------------------------------------------------------------------------
// Problem constants
// ---------------------------------------------------------------------------
#define BQ    4096
#define SRCM1 49
#define TGTQ  25
#define RQ    1024
#define HQ    67
#define IQ    82

// ---------------------------------------------------------------------------
// fp32 scratch
// ---------------------------------------------------------------------------
constexpr long long OFF_HCAT = 0;                                   // [BQ, 2R]
constexpr long long OFF_GI1  = OFF_HCAT + (long long)BQ * 2 * RQ;   // [BQ, 3R]
constexpr long long OFF_GH1  = OFF_GI1  + (long long)BQ * 3 * RQ;
constexpr long long OFF_GI2  = OFF_GH1  + (long long)BQ * 3 * RQ;
constexpr long long OFF_GH2  = OFF_GI2  + (long long)BQ * 3 * RQ;
constexpr long long OFF_X    = OFF_GH2  + (long long)BQ * 3 * RQ;   // [BQ, IQ]
constexpr long long SCRATCH_TOTAL = OFF_X + (long long)BQ * IQ;

__device__ float g_scratch[SCRATCH_TOTAL];

// ---------------------------------------------------------------------------
// bf16 split scratch: weights pre-split once per launch, hcat split in combine
// ---------------------------------------------------------------------------
constexpr long long NW = 3LL * RQ * RQ;
constexpr long long OFFB_W1H = 0;                       // Wh1 hi
constexpr long long OFFB_W1L = OFFB_W1H + NW;
constexpr long long OFFB_W2H = OFFB_W1L + NW;           // Wi2
constexpr long long OFFB_W2L = OFFB_W2H + NW;
constexpr long long OFFB_W3H = OFFB_W2L + NW;           // Wh2
constexpr long long OFFB_W3L = OFFB_W3H + NW;
constexpr long long OFFB_HH  = OFFB_W3L + NW;           // hcat hi [BQ][2R]
constexpr long long OFFB_HL  = OFFB_HH + (long long)BQ * 2 * RQ;
constexpr long long BF_TOTAL = OFFB_HL + (long long)BQ * 2 * RQ;

__device__ __nv_bfloat16 g_bf[BF_TOTAL];

// ---------------------------------------------------------------------------
// Common helpers
// ---------------------------------------------------------------------------
__device__ __forceinline__ uint32_t smem_u32(const void* p) {
    uint32_t a;
    asm("{ .reg .u64 t; cvta.to.shared.u64 t, %1; cvt.u32.u64 %0, t; }"
        : "=r"(a) : "l"(p));
    return a;
}

#define MMA_BF16(ACC, A0, A1, A2, A3, B0, B1)                                  \
    asm volatile(                                                              \
        "mma.sync.aligned.m16n8k16.row.col.f32.bf16.bf16.f32 "                 \
        "{%0,%1,%2,%3}, {%4,%5,%6,%7}, {%8,%9}, {%0,%1,%2,%3};"                \
        : "+f"((ACC)[0]), "+f"((ACC)[1]), "+f"((ACC)[2]), "+f"((ACC)[3])       \
        : "r"(A0), "r"(A1), "r"(A2), "r"(A3), "r"(B0), "r"(B1))

#define LDM_X4(R0, R1, R2, R3, ADDR)                                           \
    asm volatile(                                                              \
        "ldmatrix.sync.aligned.m8n8.x4.shared.b16 {%0,%1,%2,%3}, [%4];"        \
        : "=r"(R0), "=r"(R1), "=r"(R2), "=r"(R3) : "r"(ADDR))

__device__ __forceinline__ void cp16(uint32_t dst, const void* src) {
    asm volatile("cp.async.ca.shared.global [%0], [%1], 16;"
                 :: "r"(dst), "l"(src));
}
#define CP_COMMIT() asm volatile("cp.async.commit_group;" ::: "memory")
#define CP_WAIT0()  asm volatile("cp.async.wait_group 0;" ::: "memory")

// Swizzled smem offset inside a 128x16(bf16) tile (4KB): row r (0..127),
// 16B-half h (0..1). XOR keeps each 8-row ldmatrix phase conflict-free.
__device__ __forceinline__ uint32_t swz(int r, int h) {
    return (uint32_t)(((r >> 2) << 7) + ((r & 3) << 5) + ((h ^ ((r >> 2) & 1)) << 4));
}

// ---------------------------------------------------------------------------
// Big GEMM (bf16x3, legacy HMMA):  C[4096, 3072] = A[4096,1024] @ W[3072,1024]^T + bias
//   A/W pre-split bf16 hi/lo in g_bf. Block 128x128, BK=16, 256 threads,
//   8 warps (2M x 4N, warp tile 64x32). cp.async double buffer, ldmatrix.
//   gridDim.z = 2 fuses two independent GEMMs (gi2 + gh2).
// ---------------------------------------------------------------------------
#define GLDA (2 * RQ)     // 2048
#define GLDC (3 * RQ)     // 3072
#define GKIT 64           // K / 16

__global__ __launch_bounds__(256, 1)
void gemm_big_kernel(long long ahA, long long alA, long long whA, long long wlA,
                     const float* __restrict__ biasA, long long cA,
                     long long ahB, long long alB, long long whB, long long wlB,
                     const float* __restrict__ biasB, long long cB)
{
    __shared__ __align__(128) uint8_t sm[32768];   // 2 buffers x 4 tiles x 4KB
    const uint32_t sbase = smem_u32(sm);

    const int z = blockIdx.z;
    const __nv_bfloat16* AH = g_bf + (z ? ahB : ahA);
    const __nv_bfloat16* AL = g_bf + (z ? alB : alA);
    const __nv_bfloat16* WH = g_bf + (z ? whB : whA);
    const __nv_bfloat16* WL = g_bf + (z ? wlB : wlA);
    const float* bias = z ? biasB : biasA;
    float* C = g_scratch + (z ? cB : cA);

    const int tid  = threadIdx.x;
    const int lane = tid & 31;
    const int warp = tid >> 5;
    const int wm   = (warp >> 2) * 64;     // warp M origin (0 or 64)
    const int wn   = (warp & 3) * 32;      // warp N origin (0,32,64,96)
    const int bm   = blockIdx.y * 128;
    const int bn   = blockIdx.x * 128;

    // cp.async fill coords (4 chunks per thread, chunk i -> tile i)
    const int fr = (tid >> 1) & 127;       // row 0..127
    const int fh = tid & 1;                // 16B half

    float acc[4][4][4];
#pragma unroll
    for (int mt = 0; mt < 4; mt++)
#pragma unroll
        for (int nt = 0; nt < 4; nt++)
#pragma unroll
            for (int q = 0; q < 4; q++) acc[mt][nt][q] = 0.0f;

    auto fill = [&](int it, int buf) {
        const int k0 = it * 16;
        const uint32_t bb = sbase + buf * 16384;
        const uint32_t d = swz(fr, fh);
        const int ka = k0 + fh * 8;
        cp16(bb + d,         AH + (size_t)(bm + fr) * GLDA + ka);
        cp16(bb + 4096 + d,  AL + (size_t)(bm + fr) * GLDA + ka);
        cp16(bb + 8192 + d,  WH + (size_t)(bn + fr) * RQ + ka);
        cp16(bb + 12288 + d, WL + (size_t)(bn + fr) * RQ + ka);
        CP_COMMIT();
    };

    fill(0, 0);

    for (int it = 0; it < GKIT; it++) {
        const int b = it & 1;
        CP_WAIT0();
        __syncthreads();
        if (it + 1 < GKIT) fill(it + 1, b ^ 1);

        const uint32_t bufb = sbase + b * 16384;

        // ---- fragment loads via ldmatrix.x4 ----
        uint32_t afH[4][4], afL[4][4], bfH[4][2], bfL[4][2];
        {
            const int mrow = wm + (lane & 7) + ((lane >> 3) & 1) * 8;
            const int kh   = (lane >> 4) & 1;
#pragma unroll
            for (int mt = 0; mt < 4; mt++) {
                const uint32_t s = swz(mrow + mt * 16, kh);
                LDM_X4(afH[mt][0], afH[mt][1], afH[mt][2], afH[mt][3], bufb + s);
                LDM_X4(afL[mt][0], afL[mt][1], afL[mt][2], afL[mt][3], bufb + 4096 + s);
            }
        }
        {
            const int nrow = wn + (lane & 7) + ((lane >> 4) & 1) * 8;
            const int kh   = (lane >> 3) & 1;
#pragma unroll
            for (int p = 0; p < 2; p++) {
                const uint32_t s = swz(nrow + p * 16, kh);
                uint32_t r0, r1, r2, r3;
                LDM_X4(r0, r1, r2, r3, bufb + 8192 + s);
                bfH[2 * p][0] = r0; bfH[2 * p][1] = r1;
                bfH[2 * p + 1][0] = r2; bfH[2 * p + 1][1] = r3;
                LDM_X4(r0, r1, r2, r3, bufb + 12288 + s);
                bfL[2 * p][0] = r0; bfL[2 * p][1] = r1;
                bfL[2 * p + 1][0] = r2; bfL[2 * p + 1][1] = r3;
            }
        }

        // ---- 48 HMMA, term-major for ILP on acc ----
#pragma unroll
        for (int mt = 0; mt < 4; mt++)
#pragma unroll
            for (int nt = 0; nt < 4; nt++)
                MMA_BF16(acc[mt][nt],
                         afL[mt][0], afL[mt][1], afL[mt][2], afL[mt][3],
                         bfH[nt][0], bfH[nt][1]);
#pragma unroll
        for (int mt = 0; mt < 4; mt++)
#pragma unroll
            for (int nt = 0; nt < 4; nt++)
                MMA_BF16(acc[mt][nt],
                         afH[mt][0], afH[mt][1], afH[mt][2], afH[mt][3],
                         bfL[nt][0], bfL[nt][1]);
#pragma unroll
        for (int mt = 0; mt < 4; mt++)
#pragma unroll
            for (int nt = 0; nt < 4; nt++)
                MMA_BF16(acc[mt][nt],
                         afH[mt][0], afH[mt][1], afH[mt][2], afH[mt][3],
                         bfH[nt][0], bfH[nt][1]);
    }

    // ---- epilogue: bias, float2 stores ----
#pragma unroll
    for (int mt = 0; mt < 4; mt++) {
#pragma unroll
        for (int nt = 0; nt < 4; nt++) {
            const int n = bn + wn + nt * 8 + 2 * (lane & 3);
            const float b0 = bias[n], b1 = bias[n + 1];
#pragma unroll
            for (int h = 0; h < 2; h++) {
                const int m = bm + wm + mt * 16 + (lane >> 2) + h * 8;
                float2 v;
                v.x = acc[mt][nt][h * 2 + 0] + b0;
                v.y = acc[mt][nt][h * 2 + 1] + b1;
                *(float2*)(C + (size_t)m * GLDC + n) = v;
            }
        }
    }
}

// ---------------------------------------------------------------------------
// Legacy bf16x3 mma.sync GEMM (fp32 inputs): K=82 input GEMM and N=67 FC
// ---------------------------------------------------------------------------
#define BM 128
#define BN 64
#define BK 32

__device__ __forceinline__ void split2(float x, float y, uint32_t& hi, uint32_t& lo)
{
    __nv_bfloat162 h = __floats2bfloat162_rn(x, y);
    float xr = x - __bfloat162float(__low2bfloat16(h));
    float yr = y - __bfloat162float(__high2bfloat16(h));
    __nv_bfloat162 l = __floats2bfloat162_rn(xr, yr);
    hi = *reinterpret_cast<uint32_t*>(&h);
    lo = *reinterpret_cast<uint32_t*>(&l);
}

__global__ __launch_bounds__(256, 2)
void gemm_bf16x3_kernel(const float* __restrict__ Aext, long long Aoff, int lda,
                        const float* __restrict__ W,
                        const float* __restrict__ bias,
                        long long Roff, int res_ld,
                        float* __restrict__ Cext, long long Coff, int ldc,
                        int N, int K)
{
    const float* A = (Aoff >= 0) ? (g_scratch + Aoff) : Aext;
    float*       C = (Coff >= 0) ? (g_scratch + Coff) : Cext;
    const float* res = (Roff >= 0) ? (g_scratch + Roff) : nullptr;

    __shared__ uint32_t AsH[BK / 2][BM + 8];
    __shared__ uint32_t AsL[BK / 2][BM + 8];
    __shared__ uint32_t BsH[BK / 2][BN + 8];
    __shared__ uint32_t BsL[BK / 2][BN + 8];

    const int tid  = threadIdx.x;
    const int bm   = blockIdx.y * BM;
    const int bn   = blockIdx.x * BN;
    const int arow = tid >> 1;
    const int akh  = (tid & 1) * 16;
    const int wrow = tid >> 2;
    const int wkq  = (tid & 3) * 8;
    const int lane = tid & 31;
    const int warp = tid >> 5;
    const int wm   = (warp >> 1) * 32;
    const int wn   = (warp & 1) * 32;
    const int gid  = lane >> 2;
    const int tig  = lane & 3;

    const bool fast   = ((K & (BK - 1)) == 0) && ((lda & 3) == 0);
    const int  ktiles = (K + BK - 1) / BK;

    float acc[2][4][4];
#pragma unroll
    for (int mt = 0; mt < 2; mt++)
#pragma unroll
        for (int nt = 0; nt < 4; nt++)
#pragma unroll
            for (int q = 0; q < 4; q++) acc[mt][nt][q] = 0.0f;

    for (int kt = 0; kt < ktiles; kt++) {
        const int k0 = kt * BK;
        __syncthreads();

        float av[16];
        if (fast) {
#pragma unroll
            for (int q = 0; q < 4; q++) {
                const float4 v = *reinterpret_cast<const float4*>(
                    A + (size_t)(bm + arow) * lda + k0 + akh + q * 4);
                av[q * 4 + 0] = v.x; av[q * 4 + 1] = v.y;
                av[q * 4 + 2] = v.z; av[q * 4 + 3] = v.w;
            }
        } else {
#pragma unroll
            for (int j = 0; j < 16; j++) {
                const int k = k0 + akh + j;
                av[j] = (k < K) ? A[(size_t)(bm + arow) * lda + k] : 0.0f;
            }
        }
#pragma unroll
        for (int j = 0; j < 8; j++) {
            uint32_t hi, lo;
            split2(av[2 * j], av[2 * j + 1], hi, lo);
            AsH[akh / 2 + j][arow] = hi;
            AsL[akh / 2 + j][arow] = lo;
        }

        float wv[8];
        if (fast && (bn + wrow) < N) {
#pragma unroll
            for (int q = 0; q < 2; q++) {
                const float4 v = *reinterpret_cast<const float4*>(
                    W + (size_t)(bn + wrow) * K + k0 + wkq + q * 4);
                wv[q * 4 + 0] = v.x; wv[q * 4 + 1] = v.y;
                wv[q * 4 + 2] = v.z; wv[q * 4 + 3] = v.w;
            }
        } else {
#pragma unroll
            for (int j = 0; j < 8; j++) {
                const int k = k0 + wkq + j;
                wv[j] = (k < K && (bn + wrow) < N)
                    ? W[(size_t)(bn + wrow) * K + k] : 0.0f;
            }
        }
#pragma unroll
        for (int j = 0; j < 4; j++) {
            uint32_t hi, lo;
            split2(wv[2 * j], wv[2 * j + 1], hi, lo);
            BsH[wkq / 2 + j][wrow] = hi;
            BsL[wkq / 2 + j][wrow] = lo;
        }
        __syncthreads();

#pragma unroll
        for (int kc = 0; kc < 2; kc++) {
            const int kb = kc * 8;
            uint32_t afH[2][4], afL[2][4], bfH[4][2], bfL[4][2];
#pragma unroll
            for (int mt = 0; mt < 2; mt++) {
                const int r0 = wm + mt * 16 + gid;
                afH[mt][0] = AsH[kb + tig][r0];
                afH[mt][1] = AsH[kb + tig][r0 + 8];
                afH[mt][2] = AsH[kb + tig + 4][r0];
                afH[mt][3] = AsH[kb + tig + 4][r0 + 8];
                afL[mt][0] = AsL[kb + tig][r0];
                afL[mt][1] = AsL[kb + tig][r0 + 8];
                afL[mt][2] = AsL[kb + tig + 4][r0];
                afL[mt][3] = AsL[kb + tig + 4][r0 + 8];
            }
#pragma unroll
            for (int nt = 0; nt < 4; nt++) {
                const int c0 = wn + nt * 8 + gid;
                bfH[nt][0] = BsH[kb + tig][c0];
                bfH[nt][1] = BsH[kb + tig + 4][c0];
                bfL[nt][0] = BsL[kb + tig][c0];
                bfL[nt][1] = BsL[kb + tig + 4][c0];
            }
#pragma unroll
            for (int mt = 0; mt < 2; mt++)
#pragma unroll
                for (int nt = 0; nt < 4; nt++) {
                    MMA_BF16(acc[mt][nt],
                             afL[mt][0], afL[mt][1], afL[mt][2], afL[mt][3],
                             bfH[nt][0], bfH[nt][1]);
                    MMA_BF16(acc[mt][nt],
                             afH[mt][0], afH[mt][1], afH[mt][2], afH[mt][3],
                             bfL[nt][0], bfL[nt][1]);
                    MMA_BF16(acc[mt][nt],
                             afH[mt][0], afH[mt][1], afH[mt][2], afH[mt][3],
                             bfH[nt][0], bfH[nt][1]);
                }
        }
    }

#pragma unroll
    for (int mt = 0; mt < 2; mt++) {
#pragma unroll
        for (int nt = 0; nt < 4; nt++) {
            const int m0 = bm + wm + mt * 16 + gid;
            const int n0 = bn + wn + nt * 8 + 2 * tig;
#pragma unroll
            for (int h = 0; h < 2; h++) {
                const int m = m0 + h * 8;
#pragma unroll
                for (int q = 0; q < 2; q++) {
                    const int n = n0 + q;
                    if (n < N) {
                        float v = acc[mt][nt][h * 2 + q] + bias[n];
                        if (res) v += res[(size_t)m * res_ld + n];
                        C[(size_t)m * ldc + n] = v;
                    }
                }
            }
        }
    }
}

// ---------------------------------------------------------------------------
// GRU combine: h_new = (1-z)*n + z*h ; also writes bf16 hi/lo split of h_new
// ---------------------------------------------------------------------------
__global__ void gru_combine_kernel(long long gi_off, long long gh_off,
                                   long long h_off, long long hb)
{
    const int idx = blockIdx.x * blockDim.x + threadIdx.x;
    if (idx >= BQ * RQ) return;
    const int b = idx >> 10;
    const int j = idx & (RQ - 1);

    const float* gi = g_scratch + gi_off;
    const float* gh = g_scratch + gh_off;
    float*       h  = g_scratch + h_off;

    const size_t g = (size_t)b * 3 * RQ + j;
    const float ir = gi[g], iz = gi[g + RQ], inn = gi[g + 2 * RQ];
    const float hr = gh[g], hz = gh[g + RQ], hn  = gh[g + 2 * RQ];

    const float r = 1.0f / (1.0f + expf(-(ir + hr)));
    const float z = 1.0f / (1.0f + expf(-(iz + hz)));
    const float n = tanhf(inn + r * hn);

    const size_t hi = (size_t)b * 2 * RQ + j;
    const float hp = h[hi];
    const float v = (1.0f - z) * n + z * hp;
    h[hi] = v;

    const __nv_bfloat16 vh = __float2bfloat16(v);
    const size_t bo = (size_t)b * 2 * RQ + hb + j;
    g_bf[OFFB_HH + bo] = vh;
    g_bf[OFFB_HL + bo] = __float2bfloat16(v - __bfloat162float(vh));
}

// ---------------------------------------------------------------------------
// Weight split, decoder input assembly, zero fills
// ---------------------------------------------------------------------------
__global__ void split_w_kernel(const float* __restrict__ W,
                               long long dh, long long dl, int count)
{
    const int i = blockIdx.x * blockDim.x + threadIdx.x;
    if (i >= count) return;
    const float v = W[i];
    const __nv_bfloat16 h = __float2bfloat16(v);
    g_bf[dh + i] = h;
    g_bf[dl + i] = __float2bfloat16(v - __bfloat162float(h));
}

__global__ void build_x_kernel(const float* __restrict__ dec,
                               const float* __restrict__ out, int t)
{
    const int idx = blockIdx.x * blockDim.x + threadIdx.x;
    if (idx >= BQ * IQ) return;
    const int b = idx / IQ;
    const int i = idx - b * IQ;
    float v;
    if (t == 0) {
        v = dec[(size_t)b * TGTQ * IQ + i];
    } else if (i < HQ) {
        v = out[(size_t)(b * TGTQ + (t - 1)) * HQ + i];
    } else {
        v = dec[(size_t)(b * TGTQ + t) * IQ + i];
    }
    g_scratch[OFF_X + idx] = v;
}

__global__ void zero_kernel(long long off, long long count)
{
    const long long idx = (long long)blockIdx.x * blockDim.x + threadIdx.x;
    if (idx < count) g_scratch[off + idx] = 0.0f;
}

__global__ void zero_bf_kernel(long long off, long long count)
{
    const long long idx = (long long)blockIdx.x * blockDim.x + threadIdx.x;
    if (idx < count) g_bf[off + idx] = __float2bfloat16(0.0f);
}

// ---------------------------------------------------------------------------
// Launch
// ---------------------------------------------------------------------------
extern "C" void kernel_launch(void* const* d_in, const int* in_sizes, int n_in,
                              void* d_out, int out_size)
{
    const float* enc = (const float*)d_in[0];
    const float* dec = (const float*)d_in[1];
    const float* Wi1 = (const float*)d_in[2];
    const float* Wh1 = (const float*)d_in[3];
    const float* bi1 = (const float*)d_in[4];
    const float* bh1 = (const float*)d_in[5];
    const float* Wi2 = (const float*)d_in[6];
    const float* Wh2 = (const float*)d_in[7];
    const float* bi2 = (const float*)d_in[8];
    const float* bh2 = (const float*)d_in[9];
    const float* Wfc = (const float*)d_in[10];
    const float* bfc = (const float*)d_in[11];
    float* out = (float*)d_out;
    (void)in_sizes; (void)n_in; (void)out_size;

    const dim3 blk(256);
    const dim3 gridBig1(GLDC / 128, BQ / 128, 1);       // (24, 32, 1)
    const dim3 gridBig2(GLDC / 128, BQ / 128, 2);       // (24, 32, 2) fused
    const dim3 grid3R((3 * RQ) / BN, BQ / BM);          // (48, 32) legacy
    const dim3 gridFC((HQ + BN - 1) / BN, BQ / BM);     // (2, 32)
    const int  combine_blocks = (BQ * RQ) / 256;
    const int  bx_blocks = (BQ * IQ + 255) / 256;
    const int  wsplit_blocks = (int)((NW + 255) / 256);

    // per-launch init: zero h (fp32 + splits), split weights
    zero_kernel<<<(int)((BQ * 2LL * RQ + 255) / 256), blk>>>(OFF_HCAT, (long long)BQ * 2 * RQ);
    zero_bf_kernel<<<(int)((2LL * BQ * 2 * RQ + 255) / 256), blk>>>(OFFB_HH, 2LL * BQ * 2 * RQ);
    split_w_kernel<<<wsplit_blocks, blk>>>(Wh1, OFFB_W1H, OFFB_W1L, (int)NW);
    split_w_kernel<<<wsplit_blocks, blk>>>(Wi2, OFFB_W2H, OFFB_W2L, (int)NW);
    split_w_kernel<<<wsplit_blocks, blk>>>(Wh2, OFFB_W3H, OFFB_W3L, (int)NW);

    // ---------------- encoder: 49 steps ----------------
    for (int t = 0; t < SRCM1; t++) {
        gemm_bf16x3_kernel<<<grid3R, blk>>>(enc + (size_t)t * IQ, -1, SRCM1 * IQ,
                                            Wi1, bi1, -1, 0,
                                            nullptr, OFF_GI1, 3 * RQ, 3 * RQ, IQ);
        gemm_big_kernel<<<gridBig1, blk>>>(OFFB_HH, OFFB_HL, OFFB_W1H, OFFB_W1L,
                                           bh1, OFF_GH1,
                                           OFFB_HH, OFFB_HL, OFFB_W1H, OFFB_W1L,
                                           bh1, OFF_GH1);
        gru_combine_kernel<<<combine_blocks, blk>>>(OFF_GI1, OFF_GH1, OFF_HCAT, 0);

        gemm_big_kernel<<<gridBig2, blk>>>(OFFB_HH, OFFB_HL, OFFB_W2H, OFFB_W2L,
                                           bi2, OFF_GI2,
                                           OFFB_HH + RQ, OFFB_HL + RQ, OFFB_W3H, OFFB_W3L,
                                           bh2, OFF_GH2);
        gru_combine_kernel<<<combine_blocks, blk>>>(OFF_GI2, OFF_GH2, OFF_HCAT + RQ, RQ);
    }

    // ---------------- decoder: 25 steps ----------------
    for (int t = 0; t < TGTQ; t++) {
        build_x_kernel<<<bx_blocks, blk>>>(dec, out, t);

        gemm_bf16x3_kernel<<<grid3R, blk>>>(nullptr, OFF_X, IQ,
                                            Wi1, bi1, -1, 0,
                                            nullptr, OFF_GI1, 3 * RQ, 3 * RQ, IQ);
        gemm_big_kernel<<<gridBig1, blk>>>(OFFB_HH, OFFB_HL, OFFB_W1H, OFFB_W1L,
                                           bh1, OFF_GH1,
                                           OFFB_HH, OFFB_HL, OFFB_W1H, OFFB_W1L,
                                           bh1, OFF_GH1);
        gru_combine_kernel<<<combine_blocks, blk>>>(OFF_GI1, OFF_GH1, OFF_HCAT, 0);

        gemm_big_kernel<<<gridBig2, blk>>>(OFFB_HH, OFFB_HL, OFFB_W2H, OFFB_W2L,
                                           bi2, OFF_GI2,
                                           OFFB_HH + RQ, OFFB_HL + RQ, OFFB_W3H, OFFB_W3L,
                                           bh2, OFF_GH2);
        gru_combine_kernel<<<combine_blocks, blk>>>(OFF_GI2, OFF_GH2, OFF_HCAT + RQ, RQ);

        gemm_bf16x3_kernel<<<gridFC, blk>>>(nullptr, OFF_HCAT, 2 * RQ,
                                            Wfc, bfc, OFF_X, IQ,
                                            out + (size_t)t * HQ, -1, TGTQ * HQ,
                                            HQ, 2 * RQ);
    }
}

// round 6
// speedup vs baseline: 3.7430x; 1.2932x over previous
#include <cuda_runtime.h>
#include <cuda_bf16.h>
#include <cstdint>

// ---------------------------------------------------------------------------
// Problem constants
// ---------------------------------------------------------------------------
#define BQ    4096
#define SRCM1 49
#define TGTQ  25
#define RQ    1024
#define HQ    67
#define IQ    82

// ---------------------------------------------------------------------------
// fp32 scratch
// ---------------------------------------------------------------------------
constexpr long long OFF_HCAT = 0;                                   // [BQ, 2R]
constexpr long long OFF_GI1  = OFF_HCAT + (long long)BQ * 2 * RQ;   // [BQ, 3R]
constexpr long long OFF_GH1  = OFF_GI1  + (long long)BQ * 3 * RQ;
constexpr long long OFF_GI2  = OFF_GH1  + (long long)BQ * 3 * RQ;
constexpr long long OFF_GH2  = OFF_GI2  + (long long)BQ * 3 * RQ;
constexpr long long OFF_X    = OFF_GH2  + (long long)BQ * 3 * RQ;   // [BQ, IQ]
constexpr long long SCRATCH_TOTAL = OFF_X + (long long)BQ * IQ;

__device__ float g_scratch[SCRATCH_TOTAL];

// ---------------------------------------------------------------------------
// bf16 split scratch: weights pre-split once per launch, hcat split in combine
// ---------------------------------------------------------------------------
constexpr long long NW = 3LL * RQ * RQ;
constexpr long long OFFB_W1H = 0;                       // Wh1 hi
constexpr long long OFFB_W1L = OFFB_W1H + NW;
constexpr long long OFFB_W2H = OFFB_W1L + NW;           // Wi2
constexpr long long OFFB_W2L = OFFB_W2H + NW;
constexpr long long OFFB_W3H = OFFB_W2L + NW;           // Wh2
constexpr long long OFFB_W3L = OFFB_W3H + NW;
constexpr long long OFFB_HH  = OFFB_W3L + NW;           // hcat hi [BQ][2R]
constexpr long long OFFB_HL  = OFFB_HH + (long long)BQ * 2 * RQ;
constexpr long long BF_TOTAL = OFFB_HL + (long long)BQ * 2 * RQ;

__device__ __nv_bfloat16 g_bf[BF_TOTAL];

// ---------------------------------------------------------------------------
// Common helpers
// ---------------------------------------------------------------------------
__device__ __forceinline__ uint32_t smem_u32(const void* p) {
    uint32_t a;
    asm("{ .reg .u64 t; cvta.to.shared.u64 t, %1; cvt.u32.u64 %0, t; }"
        : "=r"(a) : "l"(p));
    return a;
}

#define MMA_BF16(ACC, A0, A1, A2, A3, B0, B1)                                  \
    asm volatile(                                                              \
        "mma.sync.aligned.m16n8k16.row.col.f32.bf16.bf16.f32 "                 \
        "{%0,%1,%2,%3}, {%4,%5,%6,%7}, {%8,%9}, {%0,%1,%2,%3};"                \
        : "+f"((ACC)[0]), "+f"((ACC)[1]), "+f"((ACC)[2]), "+f"((ACC)[3])       \
        : "r"(A0), "r"(A1), "r"(A2), "r"(A3), "r"(B0), "r"(B1))

#define LDM_X4(R0, R1, R2, R3, ADDR)                                           \
    asm volatile(                                                              \
        "ldmatrix.sync.aligned.m8n8.x4.shared.b16 {%0,%1,%2,%3}, [%4];"        \
        : "=r"(R0), "=r"(R1), "=r"(R2), "=r"(R3) : "r"(ADDR))

__device__ __forceinline__ void cp16(uint32_t dst, const void* src) {
    asm volatile("cp.async.ca.shared.global [%0], [%1], 16;"
                 :: "r"(dst), "l"(src));
}
#define CP_COMMIT() asm volatile("cp.async.commit_group;" ::: "memory")
#define CP_WAIT1()  asm volatile("cp.async.wait_group 1;" ::: "memory")

// Swizzled smem offset inside a 128x16(bf16) tile (4KB): row r (0..127),
// 16B-half h (0..1). XOR keeps each 8-row ldmatrix phase conflict-free.
__device__ __forceinline__ uint32_t swz(int r, int h) {
    return (uint32_t)(((r >> 2) << 7) + ((r & 3) << 5) + ((h ^ ((r >> 2) & 1)) << 4));
}

// ---------------------------------------------------------------------------
// Big GEMM (bf16x3, legacy HMMA):  C[4096, 3072] = A[4096,1024] @ W[3072,1024]^T
//   3-stage cp.async ring (48KB smem), ldmatrix fragments, 128x128 block,
//   8 warps (2M x 4N, warp tile 64x32). gridDim.z = 2 fuses gi2 + gh2.
// ---------------------------------------------------------------------------
#define GLDA (2 * RQ)     // 2048
#define GLDC (3 * RQ)     // 3072
#define GKIT 64           // K / 16
#define STG  3

__global__ __launch_bounds__(256, 1)
void gemm_big_kernel(long long ahA, long long alA, long long whA, long long wlA,
                     const float* __restrict__ biasA, long long cA,
                     long long ahB, long long alB, long long whB, long long wlB,
                     const float* __restrict__ biasB, long long cB)
{
    __shared__ __align__(128) uint8_t sm[STG * 16384];   // 48KB: 3 stages x 4 tiles
    const uint32_t sbase = smem_u32(sm);

    const int z = blockIdx.z;
    const __nv_bfloat16* AH = g_bf + (z ? ahB : ahA);
    const __nv_bfloat16* AL = g_bf + (z ? alB : alA);
    const __nv_bfloat16* WH = g_bf + (z ? whB : whA);
    const __nv_bfloat16* WL = g_bf + (z ? wlB : wlA);
    const float* bias = z ? biasB : biasA;
    float* C = g_scratch + (z ? cB : cA);

    const int tid  = threadIdx.x;
    const int lane = tid & 31;
    const int warp = tid >> 5;
    const int wm   = (warp >> 2) * 64;
    const int wn   = (warp & 3) * 32;
    const int bm   = blockIdx.y * 128;
    const int bn   = blockIdx.x * 128;

    // fill coords: row 0..127, 16B half
    const int fr = (tid >> 1) & 127;
    const int fh = tid & 1;
    const uint32_t fd = swz(fr, fh);
    const __nv_bfloat16* pAH = AH + (size_t)(bm + fr) * GLDA + fh * 8;
    const __nv_bfloat16* pAL = AL + (size_t)(bm + fr) * GLDA + fh * 8;
    const __nv_bfloat16* pWH = WH + (size_t)(bn + fr) * RQ + fh * 8;
    const __nv_bfloat16* pWL = WL + (size_t)(bn + fr) * RQ + fh * 8;

    // fragment smem offsets (lane-fixed)
    const int mrow = lane & 15;
    const int akh  = (lane >> 4) & 1;
    uint32_t aoff[4];
#pragma unroll
    for (int mt = 0; mt < 4; mt++) aoff[mt] = swz(wm + mt * 16 + mrow, akh);
    const int nrow = wn + (lane & 7) + ((lane >> 4) & 1) * 8;
    const int bkh  = (lane >> 3) & 1;
    uint32_t boff[2];
#pragma unroll
    for (int p = 0; p < 2; p++) boff[p] = swz(nrow + p * 16, bkh);

    float acc[4][4][4];
#pragma unroll
    for (int mt = 0; mt < 4; mt++)
#pragma unroll
        for (int nt = 0; nt < 4; nt++)
#pragma unroll
            for (int q = 0; q < 4; q++) acc[mt][nt][q] = 0.0f;

    auto fill = [&](int it) {
        if (it < GKIT) {
            const uint32_t bb = sbase + (it % STG) * 16384;
            const int k = it * 16;
            cp16(bb + fd,         pAH + k);
            cp16(bb + 4096 + fd,  pAL + k);
            cp16(bb + 8192 + fd,  pWH + k);
            cp16(bb + 12288 + fd, pWL + k);
        }
        CP_COMMIT();   // unconditional: empty tail groups keep count algebra simple
    };

    fill(0);
    fill(1);

    for (int it = 0; it < GKIT; it++) {
        CP_WAIT1();            // stage it ready (<=1 pending: it+1 may be in flight)
        __syncthreads();
        fill(it + 2);          // overwrites stage (it-1)%3: computed by all warps

        const uint32_t bufb = sbase + (it % STG) * 16384;

        // B fragments for all 4 n-tiles
        uint32_t bfH[4][2], bfL[4][2];
#pragma unroll
        for (int p = 0; p < 2; p++) {
            uint32_t r0, r1, r2, r3;
            LDM_X4(r0, r1, r2, r3, bufb + 8192 + boff[p]);
            bfH[2 * p][0] = r0; bfH[2 * p][1] = r1;
            bfH[2 * p + 1][0] = r2; bfH[2 * p + 1][1] = r3;
            LDM_X4(r0, r1, r2, r3, bufb + 12288 + boff[p]);
            bfL[2 * p][0] = r0; bfL[2 * p][1] = r1;
            bfL[2 * p + 1][0] = r2; bfL[2 * p + 1][1] = r3;
        }

        // A fragments per m-tile; 12 HMMA per m-tile (3 split terms x 4 n-tiles)
#pragma unroll
        for (int mt = 0; mt < 4; mt++) {
            uint32_t aH[4], aL[4];
            LDM_X4(aH[0], aH[1], aH[2], aH[3], bufb + aoff[mt]);
            LDM_X4(aL[0], aL[1], aL[2], aL[3], bufb + 4096 + aoff[mt]);
#pragma unroll
            for (int nt = 0; nt < 4; nt++)
                MMA_BF16(acc[mt][nt], aL[0], aL[1], aL[2], aL[3],
                         bfH[nt][0], bfH[nt][1]);
#pragma unroll
            for (int nt = 0; nt < 4; nt++)
                MMA_BF16(acc[mt][nt], aH[0], aH[1], aH[2], aH[3],
                         bfL[nt][0], bfL[nt][1]);
#pragma unroll
            for (int nt = 0; nt < 4; nt++)
                MMA_BF16(acc[mt][nt], aH[0], aH[1], aH[2], aH[3],
                         bfH[nt][0], bfH[nt][1]);
        }
    }

    // epilogue: bias, float2 stores
#pragma unroll
    for (int mt = 0; mt < 4; mt++) {
#pragma unroll
        for (int nt = 0; nt < 4; nt++) {
            const int n = bn + wn + nt * 8 + 2 * (lane & 3);
            const float b0 = bias[n], b1 = bias[n + 1];
#pragma unroll
            for (int h = 0; h < 2; h++) {
                const int m = bm + wm + mt * 16 + (lane >> 2) + h * 8;
                float2 v;
                v.x = acc[mt][nt][h * 2 + 0] + b0;
                v.y = acc[mt][nt][h * 2 + 1] + b1;
                *(float2*)(C + (size_t)m * GLDC + n) = v;
            }
        }
    }
}

// ---------------------------------------------------------------------------
// Legacy bf16x3 mma.sync GEMM (fp32 inputs): K=82 input GEMM and N=67 FC
// ---------------------------------------------------------------------------
#define BM 128
#define BN 64
#define BK 32

__device__ __forceinline__ void split2(float x, float y, uint32_t& hi, uint32_t& lo)
{
    __nv_bfloat162 h = __floats2bfloat162_rn(x, y);
    float xr = x - __bfloat162float(__low2bfloat16(h));
    float yr = y - __bfloat162float(__high2bfloat16(h));
    __nv_bfloat162 l = __floats2bfloat162_rn(xr, yr);
    hi = *reinterpret_cast<uint32_t*>(&h);
    lo = *reinterpret_cast<uint32_t*>(&l);
}

__global__ __launch_bounds__(256, 2)
void gemm_bf16x3_kernel(const float* __restrict__ Aext, long long Aoff, int lda,
                        const float* __restrict__ W,
                        const float* __restrict__ bias,
                        long long Roff, int res_ld,
                        float* __restrict__ Cext, long long Coff, int ldc,
                        int N, int K)
{
    const float* A = (Aoff >= 0) ? (g_scratch + Aoff) : Aext;
    float*       C = (Coff >= 0) ? (g_scratch + Coff) : Cext;
    const float* res = (Roff >= 0) ? (g_scratch + Roff) : nullptr;

    __shared__ uint32_t AsH[BK / 2][BM + 8];
    __shared__ uint32_t AsL[BK / 2][BM + 8];
    __shared__ uint32_t BsH[BK / 2][BN + 8];
    __shared__ uint32_t BsL[BK / 2][BN + 8];

    const int tid  = threadIdx.x;
    const int bm   = blockIdx.y * BM;
    const int bn   = blockIdx.x * BN;
    const int arow = tid >> 1;
    const int akh  = (tid & 1) * 16;
    const int wrow = tid >> 2;
    const int wkq  = (tid & 3) * 8;
    const int lane = tid & 31;
    const int warp = tid >> 5;
    const int wm   = (warp >> 1) * 32;
    const int wn   = (warp & 1) * 32;
    const int gid  = lane >> 2;
    const int tig  = lane & 3;

    const bool fast   = ((K & (BK - 1)) == 0) && ((lda & 3) == 0);
    const int  ktiles = (K + BK - 1) / BK;

    float acc[2][4][4];
#pragma unroll
    for (int mt = 0; mt < 2; mt++)
#pragma unroll
        for (int nt = 0; nt < 4; nt++)
#pragma unroll
            for (int q = 0; q < 4; q++) acc[mt][nt][q] = 0.0f;

    for (int kt = 0; kt < ktiles; kt++) {
        const int k0 = kt * BK;
        __syncthreads();

        float av[16];
        if (fast) {
#pragma unroll
            for (int q = 0; q < 4; q++) {
                const float4 v = *reinterpret_cast<const float4*>(
                    A + (size_t)(bm + arow) * lda + k0 + akh + q * 4);
                av[q * 4 + 0] = v.x; av[q * 4 + 1] = v.y;
                av[q * 4 + 2] = v.z; av[q * 4 + 3] = v.w;
            }
        } else {
#pragma unroll
            for (int j = 0; j < 16; j++) {
                const int k = k0 + akh + j;
                av[j] = (k < K) ? A[(size_t)(bm + arow) * lda + k] : 0.0f;
            }
        }
#pragma unroll
        for (int j = 0; j < 8; j++) {
            uint32_t hi, lo;
            split2(av[2 * j], av[2 * j + 1], hi, lo);
            AsH[akh / 2 + j][arow] = hi;
            AsL[akh / 2 + j][arow] = lo;
        }

        float wv[8];
        if (fast && (bn + wrow) < N) {
#pragma unroll
            for (int q = 0; q < 2; q++) {
                const float4 v = *reinterpret_cast<const float4*>(
                    W + (size_t)(bn + wrow) * K + k0 + wkq + q * 4);
                wv[q * 4 + 0] = v.x; wv[q * 4 + 1] = v.y;
                wv[q * 4 + 2] = v.z; wv[q * 4 + 3] = v.w;
            }
        } else {
#pragma unroll
            for (int j = 0; j < 8; j++) {
                const int k = k0 + wkq + j;
                wv[j] = (k < K && (bn + wrow) < N)
                    ? W[(size_t)(bn + wrow) * K + k] : 0.0f;
            }
        }
#pragma unroll
        for (int j = 0; j < 4; j++) {
            uint32_t hi, lo;
            split2(wv[2 * j], wv[2 * j + 1], hi, lo);
            BsH[wkq / 2 + j][wrow] = hi;
            BsL[wkq / 2 + j][wrow] = lo;
        }
        __syncthreads();

#pragma unroll
        for (int kc = 0; kc < 2; kc++) {
            const int kb = kc * 8;
            uint32_t afH[2][4], afL[2][4], bfH[4][2], bfL[4][2];
#pragma unroll
            for (int mt = 0; mt < 2; mt++) {
                const int r0 = wm + mt * 16 + gid;
                afH[mt][0] = AsH[kb + tig][r0];
                afH[mt][1] = AsH[kb + tig][r0 + 8];
                afH[mt][2] = AsH[kb + tig + 4][r0];
                afH[mt][3] = AsH[kb + tig + 4][r0 + 8];
                afL[mt][0] = AsL[kb + tig][r0];
                afL[mt][1] = AsL[kb + tig][r0 + 8];
                afL[mt][2] = AsL[kb + tig + 4][r0];
                afL[mt][3] = AsL[kb + tig + 4][r0 + 8];
            }
#pragma unroll
            for (int nt = 0; nt < 4; nt++) {
                const int c0 = wn + nt * 8 + gid;
                bfH[nt][0] = BsH[kb + tig][c0];
                bfH[nt][1] = BsH[kb + tig + 4][c0];
                bfL[nt][0] = BsL[kb + tig][c0];
                bfL[nt][1] = BsL[kb + tig + 4][c0];
            }
#pragma unroll
            for (int mt = 0; mt < 2; mt++)
#pragma unroll
                for (int nt = 0; nt < 4; nt++) {
                    MMA_BF16(acc[mt][nt],
                             afL[mt][0], afL[mt][1], afL[mt][2], afL[mt][3],
                             bfH[nt][0], bfH[nt][1]);
                    MMA_BF16(acc[mt][nt],
                             afH[mt][0], afH[mt][1], afH[mt][2], afH[mt][3],
                             bfL[nt][0], bfL[nt][1]);
                    MMA_BF16(acc[mt][nt],
                             afH[mt][0], afH[mt][1], afH[mt][2], afH[mt][3],
                             bfH[nt][0], bfH[nt][1]);
                }
        }
    }

#pragma unroll
    for (int mt = 0; mt < 2; mt++) {
#pragma unroll
        for (int nt = 0; nt < 4; nt++) {
            const int m0 = bm + wm + mt * 16 + gid;
            const int n0 = bn + wn + nt * 8 + 2 * tig;
#pragma unroll
            for (int h = 0; h < 2; h++) {
                const int m = m0 + h * 8;
#pragma unroll
                for (int q = 0; q < 2; q++) {
                    const int n = n0 + q;
                    if (n < N) {
                        float v = acc[mt][nt][h * 2 + q] + bias[n];
                        if (res) v += res[(size_t)m * res_ld + n];
                        C[(size_t)m * ldc + n] = v;
                    }
                }
            }
        }
    }
}

// ---------------------------------------------------------------------------
// GRU combine: h_new = (1-z)*n + z*h ; also writes bf16 hi/lo split of h_new
// ---------------------------------------------------------------------------
__global__ void gru_combine_kernel(long long gi_off, long long gh_off,
                                   long long h_off, long long hb)
{
    const int idx = blockIdx.x * blockDim.x + threadIdx.x;
    if (idx >= BQ * RQ) return;
    const int b = idx >> 10;
    const int j = idx & (RQ - 1);

    const float* gi = g_scratch + gi_off;
    const float* gh = g_scratch + gh_off;
    float*       h  = g_scratch + h_off;

    const size_t g = (size_t)b * 3 * RQ + j;
    const float ir = gi[g], iz = gi[g + RQ], inn = gi[g + 2 * RQ];
    const float hr = gh[g], hz = gh[g + RQ], hn  = gh[g + 2 * RQ];

    const float r = 1.0f / (1.0f + expf(-(ir + hr)));
    const float z = 1.0f / (1.0f + expf(-(iz + hz)));
    const float n = tanhf(inn + r * hn);

    const size_t hi = (size_t)b * 2 * RQ + j;
    const float hp = h[hi];
    const float v = (1.0f - z) * n + z * hp;
    h[hi] = v;

    const __nv_bfloat16 vh = __float2bfloat16(v);
    const size_t bo = (size_t)b * 2 * RQ + hb + j;
    g_bf[OFFB_HH + bo] = vh;
    g_bf[OFFB_HL + bo] = __float2bfloat16(v - __bfloat162float(vh));
}

// ---------------------------------------------------------------------------
// Weight split, decoder input assembly, zero fills
// ---------------------------------------------------------------------------
__global__ void split_w_kernel(const float* __restrict__ W,
                               long long dh, long long dl, int count)
{
    const int i = blockIdx.x * blockDim.x + threadIdx.x;
    if (i >= count) return;
    const float v = W[i];
    const __nv_bfloat16 h = __float2bfloat16(v);
    g_bf[dh + i] = h;
    g_bf[dl + i] = __float2bfloat16(v - __bfloat162float(h));
}

__global__ void build_x_kernel(const float* __restrict__ dec,
                               const float* __restrict__ out, int t)
{
    const int idx = blockIdx.x * blockDim.x + threadIdx.x;
    if (idx >= BQ * IQ) return;
    const int b = idx / IQ;
    const int i = idx - b * IQ;
    float v;
    if (t == 0) {
        v = dec[(size_t)b * TGTQ * IQ + i];
    } else if (i < HQ) {
        v = out[(size_t)(b * TGTQ + (t - 1)) * HQ + i];
    } else {
        v = dec[(size_t)(b * TGTQ + t) * IQ + i];
    }
    g_scratch[OFF_X + idx] = v;
}

__global__ void zero_kernel(long long off, long long count)
{
    const long long idx = (long long)blockIdx.x * blockDim.x + threadIdx.x;
    if (idx < count) g_scratch[off + idx] = 0.0f;
}

__global__ void zero_bf_kernel(long long off, long long count)
{
    const long long idx = (long long)blockIdx.x * blockDim.x + threadIdx.x;
    if (idx < count) g_bf[off + idx] = __float2bfloat16(0.0f);
}

// ---------------------------------------------------------------------------
// Launch
// ---------------------------------------------------------------------------
extern "C" void kernel_launch(void* const* d_in, const int* in_sizes, int n_in,
                              void* d_out, int out_size)
{
    const float* enc = (const float*)d_in[0];
    const float* dec = (const float*)d_in[1];
    const float* Wi1 = (const float*)d_in[2];
    const float* Wh1 = (const float*)d_in[3];
    const float* bi1 = (const float*)d_in[4];
    const float* bh1 = (const float*)d_in[5];
    const float* Wi2 = (const float*)d_in[6];
    const float* Wh2 = (const float*)d_in[7];
    const float* bi2 = (const float*)d_in[8];
    const float* bh2 = (const float*)d_in[9];
    const float* Wfc = (const float*)d_in[10];
    const float* bfc = (const float*)d_in[11];
    float* out = (float*)d_out;
    (void)in_sizes; (void)n_in; (void)out_size;

    const dim3 blk(256);
    const dim3 gridBig1(GLDC / 128, BQ / 128, 1);       // (24, 32, 1)
    const dim3 gridBig2(GLDC / 128, BQ / 128, 2);       // (24, 32, 2) fused
    const dim3 grid3R((3 * RQ) / BN, BQ / BM);          // (48, 32) legacy
    const dim3 gridFC((HQ + BN - 1) / BN, BQ / BM);     // (2, 32)
    const int  combine_blocks = (BQ * RQ) / 256;
    const int  bx_blocks = (BQ * IQ + 255) / 256;
    const int  wsplit_blocks = (int)((NW + 255) / 256);

    // per-launch init: zero h (fp32 + splits), split weights
    zero_kernel<<<(int)((BQ * 2LL * RQ + 255) / 256), blk>>>(OFF_HCAT, (long long)BQ * 2 * RQ);
    zero_bf_kernel<<<(int)((2LL * BQ * 2 * RQ + 255) / 256), blk>>>(OFFB_HH, 2LL * BQ * 2 * RQ);
    split_w_kernel<<<wsplit_blocks, blk>>>(Wh1, OFFB_W1H, OFFB_W1L, (int)NW);
    split_w_kernel<<<wsplit_blocks, blk>>>(Wi2, OFFB_W2H, OFFB_W2L, (int)NW);
    split_w_kernel<<<wsplit_blocks, blk>>>(Wh2, OFFB_W3H, OFFB_W3L, (int)NW);

    // ---------------- encoder: 49 steps ----------------
    for (int t = 0; t < SRCM1; t++) {
        gemm_bf16x3_kernel<<<grid3R, blk>>>(enc + (size_t)t * IQ, -1, SRCM1 * IQ,
                                            Wi1, bi1, -1, 0,
                                            nullptr, OFF_GI1, 3 * RQ, 3 * RQ, IQ);
        gemm_big_kernel<<<gridBig1, blk>>>(OFFB_HH, OFFB_HL, OFFB_W1H, OFFB_W1L,
                                           bh1, OFF_GH1,
                                           OFFB_HH, OFFB_HL, OFFB_W1H, OFFB_W1L,
                                           bh1, OFF_GH1);
        gru_combine_kernel<<<combine_blocks, blk>>>(OFF_GI1, OFF_GH1, OFF_HCAT, 0);

        gemm_big_kernel<<<gridBig2, blk>>>(OFFB_HH, OFFB_HL, OFFB_W2H, OFFB_W2L,
                                           bi2, OFF_GI2,
                                           OFFB_HH + RQ, OFFB_HL + RQ, OFFB_W3H, OFFB_W3L,
                                           bh2, OFF_GH2);
        gru_combine_kernel<<<combine_blocks, blk>>>(OFF_GI2, OFF_GH2, OFF_HCAT + RQ, RQ);
    }

    // ---------------- decoder: 25 steps ----------------
    for (int t = 0; t < TGTQ; t++) {
        build_x_kernel<<<bx_blocks, blk>>>(dec, out, t);

        gemm_bf16x3_kernel<<<grid3R, blk>>>(nullptr, OFF_X, IQ,
                                            Wi1, bi1, -1, 0,
                                            nullptr, OFF_GI1, 3 * RQ, 3 * RQ, IQ);
        gemm_big_kernel<<<gridBig1, blk>>>(OFFB_HH, OFFB_HL, OFFB_W1H, OFFB_W1L,
                                           bh1, OFF_GH1,
                                           OFFB_HH, OFFB_HL, OFFB_W1H, OFFB_W1L,
                                           bh1, OFF_GH1);
        gru_combine_kernel<<<combine_blocks, blk>>>(OFF_GI1, OFF_GH1, OFF_HCAT, 0);

        gemm_big_kernel<<<gridBig2, blk>>>(OFFB_HH, OFFB_HL, OFFB_W2H, OFFB_W2L,
                                           bi2, OFF_GI2,
                                           OFFB_HH + RQ, OFFB_HL + RQ, OFFB_W3H, OFFB_W3L,
                                           bh2, OFF_GH2);
        gru_combine_kernel<<<combine_blocks, blk>>>(OFF_GI2, OFF_GH2, OFF_HCAT + RQ, RQ);

        gemm_bf16x3_kernel<<<gridFC, blk>>>(nullptr, OFF_HCAT, 2 * RQ,
                                            Wfc, bfc, OFF_X, IQ,
                                            out + (size_t)t * HQ, -1, TGTQ * HQ,
                                            HQ, 2 * RQ);
    }
}

// round 7
// speedup vs baseline: 4.2085x; 1.1244x over previous
#include <cuda_runtime.h>
#include <cuda_bf16.h>
#include <cstdint>

// ---------------------------------------------------------------------------
// Problem constants
// ---------------------------------------------------------------------------
#define BQ    4096
#define SRCM1 49
#define TGTQ  25
#define RQ    1024
#define HQ    67
#define IQ    82

// ---------------------------------------------------------------------------
// fp32 scratch
// ---------------------------------------------------------------------------
constexpr long long OFF_HCAT = 0;                                   // [BQ, 2R]
constexpr long long OFF_GI1  = OFF_HCAT + (long long)BQ * 2 * RQ;   // [BQ, 3R] (decoder)
constexpr long long OFF_GH1  = OFF_GI1  + (long long)BQ * 3 * RQ;
constexpr long long OFF_GI2  = OFF_GH1  + (long long)BQ * 3 * RQ;
constexpr long long OFF_GH2  = OFF_GI2  + (long long)BQ * 3 * RQ;
constexpr long long OFF_X    = OFF_GH2  + (long long)BQ * 3 * RQ;   // [BQ, IQ]
constexpr long long OFF_GIALL= OFF_X    + (long long)BQ * IQ;       // [BQ*49, 3R] encoder gi1
constexpr long long SCRATCH_TOTAL = OFF_GIALL + (long long)BQ * SRCM1 * 3 * RQ;

__device__ float g_scratch[SCRATCH_TOTAL];

// ---------------------------------------------------------------------------
// bf16 split scratch: weights pre-split once per launch, hcat split in combine
// ---------------------------------------------------------------------------
constexpr long long NW = 3LL * RQ * RQ;
constexpr long long OFFB_W1H = 0;                       // Wh1 hi
constexpr long long OFFB_W1L = OFFB_W1H + NW;
constexpr long long OFFB_W2H = OFFB_W1L + NW;           // Wi2
constexpr long long OFFB_W2L = OFFB_W2H + NW;
constexpr long long OFFB_W3H = OFFB_W2L + NW;           // Wh2
constexpr long long OFFB_W3L = OFFB_W3H + NW;
constexpr long long OFFB_HH  = OFFB_W3L + NW;           // hcat hi [BQ][2R]
constexpr long long OFFB_HL  = OFFB_HH + (long long)BQ * 2 * RQ;
constexpr long long BF_TOTAL = OFFB_HL + (long long)BQ * 2 * RQ;

__device__ __nv_bfloat16 g_bf[BF_TOTAL];

// ---------------------------------------------------------------------------
// Common helpers
// ---------------------------------------------------------------------------
__device__ __forceinline__ uint32_t smem_u32(const void* p) {
    uint32_t a;
    asm("{ .reg .u64 t; cvta.to.shared.u64 t, %1; cvt.u32.u64 %0, t; }"
        : "=r"(a) : "l"(p));
    return a;
}

#define MMA_BF16(ACC, A0, A1, A2, A3, B0, B1)                                  \
    asm volatile(                                                              \
        "mma.sync.aligned.m16n8k16.row.col.f32.bf16.bf16.f32 "                 \
        "{%0,%1,%2,%3}, {%4,%5,%6,%7}, {%8,%9}, {%0,%1,%2,%3};"                \
        : "+f"((ACC)[0]), "+f"((ACC)[1]), "+f"((ACC)[2]), "+f"((ACC)[3])       \
        : "r"(A0), "r"(A1), "r"(A2), "r"(A3), "r"(B0), "r"(B1))

#define LDM_X4(R0, R1, R2, R3, ADDR)                                           \
    asm volatile(                                                              \
        "ldmatrix.sync.aligned.m8n8.x4.shared.b16 {%0,%1,%2,%3}, [%4];"        \
        : "=r"(R0), "=r"(R1), "=r"(R2), "=r"(R3) : "r"(ADDR))

__device__ __forceinline__ void cp16(uint32_t dst, const void* src) {
    asm volatile("cp.async.ca.shared.global [%0], [%1], 16;"
                 :: "r"(dst), "l"(src));
}
#define CP_COMMIT() asm volatile("cp.async.commit_group;" ::: "memory")
#define CP_WAIT1()  asm volatile("cp.async.wait_group 1;" ::: "memory")

// Swizzled smem offset inside a 128x16(bf16) tile (4KB): row r (0..127),
// 16B-half h (0..1). XOR keeps each 8-row ldmatrix phase conflict-free.
__device__ __forceinline__ uint32_t swz(int r, int h) {
    return (uint32_t)(((r >> 2) << 7) + ((r & 3) << 5) + ((h ^ ((r >> 2) & 1)) << 4));
}

// ---------------------------------------------------------------------------
// Big GEMM (bf16x3, legacy HMMA):  C[4096, 3072] = A[4096,1024] @ W[3072,1024]^T
//   3-stage cp.async ring (48KB smem), ldmatrix fragments, 128x128 block,
//   8 warps (2M x 4N, warp tile 64x32). gridDim.z = 2 fuses gi2 + gh2.
//   occupancy 2: co-resident CTA covers wait_group/syncthreads bubbles.
// ---------------------------------------------------------------------------
#define GLDA (2 * RQ)     // 2048
#define GLDC (3 * RQ)     // 3072
#define GKIT 64           // K / 16
#define STG  3

__global__ __launch_bounds__(256, 2)
void gemm_big_kernel(long long ahA, long long alA, long long whA, long long wlA,
                     const float* __restrict__ biasA, long long cA,
                     long long ahB, long long alB, long long whB, long long wlB,
                     const float* __restrict__ biasB, long long cB)
{
    __shared__ __align__(128) uint8_t sm[STG * 16384];   // 48KB: 3 stages x 4 tiles
    const uint32_t sbase = smem_u32(sm);

    const int z = blockIdx.z;
    const __nv_bfloat16* AH = g_bf + (z ? ahB : ahA);
    const __nv_bfloat16* AL = g_bf + (z ? alB : alA);
    const __nv_bfloat16* WH = g_bf + (z ? whB : whA);
    const __nv_bfloat16* WL = g_bf + (z ? wlB : wlA);
    const float* bias = z ? biasB : biasA;
    float* C = g_scratch + (z ? cB : cA);

    const int tid  = threadIdx.x;
    const int lane = tid & 31;
    const int warp = tid >> 5;
    const int wm   = (warp >> 2) * 64;
    const int wn   = (warp & 3) * 32;
    const int bm   = blockIdx.y * 128;
    const int bn   = blockIdx.x * 128;

    // fill coords: row 0..127, 16B half
    const int fr = (tid >> 1) & 127;
    const int fh = tid & 1;
    const uint32_t fd = swz(fr, fh);
    const __nv_bfloat16* pAH = AH + (size_t)(bm + fr) * GLDA + fh * 8;
    const __nv_bfloat16* pAL = AL + (size_t)(bm + fr) * GLDA + fh * 8;
    const __nv_bfloat16* pWH = WH + (size_t)(bn + fr) * RQ + fh * 8;
    const __nv_bfloat16* pWL = WL + (size_t)(bn + fr) * RQ + fh * 8;

    // fragment smem offsets (lane-fixed)
    const int mrow = lane & 15;
    const int akh  = (lane >> 4) & 1;
    uint32_t aoff[4];
#pragma unroll
    for (int mt = 0; mt < 4; mt++) aoff[mt] = swz(wm + mt * 16 + mrow, akh);
    const int nrow = wn + (lane & 7) + ((lane >> 4) & 1) * 8;
    const int bkh  = (lane >> 3) & 1;
    uint32_t boff[2];
#pragma unroll
    for (int p = 0; p < 2; p++) boff[p] = swz(nrow + p * 16, bkh);

    float acc[4][4][4];
#pragma unroll
    for (int mt = 0; mt < 4; mt++)
#pragma unroll
        for (int nt = 0; nt < 4; nt++)
#pragma unroll
            for (int q = 0; q < 4; q++) acc[mt][nt][q] = 0.0f;

    auto fill = [&](int it) {
        if (it < GKIT) {
            const uint32_t bb = sbase + (it % STG) * 16384;
            const int k = it * 16;
            cp16(bb + fd,         pAH + k);
            cp16(bb + 4096 + fd,  pAL + k);
            cp16(bb + 8192 + fd,  pWH + k);
            cp16(bb + 12288 + fd, pWL + k);
        }
        CP_COMMIT();   // unconditional: empty tail groups keep count algebra simple
    };

    fill(0);
    fill(1);

    for (int it = 0; it < GKIT; it++) {
        CP_WAIT1();            // stage it ready (<=1 pending: it+1 may be in flight)
        __syncthreads();
        fill(it + 2);          // overwrites stage (it-1)%3: computed by all warps

        const uint32_t bufb = sbase + (it % STG) * 16384;

        // B fragments for all 4 n-tiles
        uint32_t bfH[4][2], bfL[4][2];
#pragma unroll
        for (int p = 0; p < 2; p++) {
            uint32_t r0, r1, r2, r3;
            LDM_X4(r0, r1, r2, r3, bufb + 8192 + boff[p]);
            bfH[2 * p][0] = r0; bfH[2 * p][1] = r1;
            bfH[2 * p + 1][0] = r2; bfH[2 * p + 1][1] = r3;
            LDM_X4(r0, r1, r2, r3, bufb + 12288 + boff[p]);
            bfL[2 * p][0] = r0; bfL[2 * p][1] = r1;
            bfL[2 * p + 1][0] = r2; bfL[2 * p + 1][1] = r3;
        }

        // A fragments per m-tile; 12 HMMA per m-tile (3 split terms x 4 n-tiles)
#pragma unroll
        for (int mt = 0; mt < 4; mt++) {
            uint32_t aH[4], aL[4];
            LDM_X4(aH[0], aH[1], aH[2], aH[3], bufb + aoff[mt]);
            LDM_X4(aL[0], aL[1], aL[2], aL[3], bufb + 4096 + aoff[mt]);
#pragma unroll
            for (int nt = 0; nt < 4; nt++)
                MMA_BF16(acc[mt][nt], aL[0], aL[1], aL[2], aL[3],
                         bfH[nt][0], bfH[nt][1]);
#pragma unroll
            for (int nt = 0; nt < 4; nt++)
                MMA_BF16(acc[mt][nt], aH[0], aH[1], aH[2], aH[3],
                         bfL[nt][0], bfL[nt][1]);
#pragma unroll
            for (int nt = 0; nt < 4; nt++)
                MMA_BF16(acc[mt][nt], aH[0], aH[1], aH[2], aH[3],
                         bfH[nt][0], bfH[nt][1]);
        }
    }

    // epilogue: bias, float2 stores
#pragma unroll
    for (int mt = 0; mt < 4; mt++) {
#pragma unroll
        for (int nt = 0; nt < 4; nt++) {
            const int n = bn + wn + nt * 8 + 2 * (lane & 3);
            const float b0 = bias[n], b1 = bias[n + 1];
#pragma unroll
            for (int h = 0; h < 2; h++) {
                const int m = bm + wm + mt * 16 + (lane >> 2) + h * 8;
                float2 v;
                v.x = acc[mt][nt][h * 2 + 0] + b0;
                v.y = acc[mt][nt][h * 2 + 1] + b1;
                *(float2*)(C + (size_t)m * GLDC + n) = v;
            }
        }
    }
}

// ---------------------------------------------------------------------------
// Legacy bf16x3 mma.sync GEMM (fp32 inputs): K=82 input GEMMs and N=67 FC
// ---------------------------------------------------------------------------
#define BM 128
#define BN 64
#define BK 32

__device__ __forceinline__ void split2(float x, float y, uint32_t& hi, uint32_t& lo)
{
    __nv_bfloat162 h = __floats2bfloat162_rn(x, y);
    float xr = x - __bfloat162float(__low2bfloat16(h));
    float yr = y - __bfloat162float(__high2bfloat16(h));
    __nv_bfloat162 l = __floats2bfloat162_rn(xr, yr);
    hi = *reinterpret_cast<uint32_t*>(&h);
    lo = *reinterpret_cast<uint32_t*>(&l);
}

__global__ __launch_bounds__(256, 2)
void gemm_bf16x3_kernel(const float* __restrict__ Aext, long long Aoff, int lda,
                        const float* __restrict__ W,
                        const float* __restrict__ bias,
                        long long Roff, int res_ld,
                        float* __restrict__ Cext, long long Coff, int ldc,
                        int N, int K)
{
    const float* A = (Aoff >= 0) ? (g_scratch + Aoff) : Aext;
    float*       C = (Coff >= 0) ? (g_scratch + Coff) : Cext;
    const float* res = (Roff >= 0) ? (g_scratch + Roff) : nullptr;

    __shared__ uint32_t AsH[BK / 2][BM + 8];
    __shared__ uint32_t AsL[BK / 2][BM + 8];
    __shared__ uint32_t BsH[BK / 2][BN + 8];
    __shared__ uint32_t BsL[BK / 2][BN + 8];

    const int tid  = threadIdx.x;
    const int bm   = blockIdx.y * BM;
    const int bn   = blockIdx.x * BN;
    const int arow = tid >> 1;
    const int akh  = (tid & 1) * 16;
    const int wrow = tid >> 2;
    const int wkq  = (tid & 3) * 8;
    const int lane = tid & 31;
    const int warp = tid >> 5;
    const int wm   = (warp >> 1) * 32;
    const int wn   = (warp & 1) * 32;
    const int gid  = lane >> 2;
    const int tig  = lane & 3;

    const bool fast   = ((K & (BK - 1)) == 0) && ((lda & 3) == 0);
    const int  ktiles = (K + BK - 1) / BK;

    float acc[2][4][4];
#pragma unroll
    for (int mt = 0; mt < 2; mt++)
#pragma unroll
        for (int nt = 0; nt < 4; nt++)
#pragma unroll
            for (int q = 0; q < 4; q++) acc[mt][nt][q] = 0.0f;

    for (int kt = 0; kt < ktiles; kt++) {
        const int k0 = kt * BK;
        __syncthreads();

        float av[16];
        if (fast) {
#pragma unroll
            for (int q = 0; q < 4; q++) {
                const float4 v = *reinterpret_cast<const float4*>(
                    A + (size_t)(bm + arow) * lda + k0 + akh + q * 4);
                av[q * 4 + 0] = v.x; av[q * 4 + 1] = v.y;
                av[q * 4 + 2] = v.z; av[q * 4 + 3] = v.w;
            }
        } else {
#pragma unroll
            for (int j = 0; j < 16; j++) {
                const int k = k0 + akh + j;
                av[j] = (k < K) ? A[(size_t)(bm + arow) * lda + k] : 0.0f;
            }
        }
#pragma unroll
        for (int j = 0; j < 8; j++) {
            uint32_t hi, lo;
            split2(av[2 * j], av[2 * j + 1], hi, lo);
            AsH[akh / 2 + j][arow] = hi;
            AsL[akh / 2 + j][arow] = lo;
        }

        float wv[8];
        if (fast && (bn + wrow) < N) {
#pragma unroll
            for (int q = 0; q < 2; q++) {
                const float4 v = *reinterpret_cast<const float4*>(
                    W + (size_t)(bn + wrow) * K + k0 + wkq + q * 4);
                wv[q * 4 + 0] = v.x; wv[q * 4 + 1] = v.y;
                wv[q * 4 + 2] = v.z; wv[q * 4 + 3] = v.w;
            }
        } else {
#pragma unroll
            for (int j = 0; j < 8; j++) {
                const int k = k0 + wkq + j;
                wv[j] = (k < K && (bn + wrow) < N)
                    ? W[(size_t)(bn + wrow) * K + k] : 0.0f;
            }
        }
#pragma unroll
        for (int j = 0; j < 4; j++) {
            uint32_t hi, lo;
            split2(wv[2 * j], wv[2 * j + 1], hi, lo);
            BsH[wkq / 2 + j][wrow] = hi;
            BsL[wkq / 2 + j][wrow] = lo;
        }
        __syncthreads();

#pragma unroll
        for (int kc = 0; kc < 2; kc++) {
            const int kb = kc * 8;
            uint32_t afH[2][4], afL[2][4], bfH[4][2], bfL[4][2];
#pragma unroll
            for (int mt = 0; mt < 2; mt++) {
                const int r0 = wm + mt * 16 + gid;
                afH[mt][0] = AsH[kb + tig][r0];
                afH[mt][1] = AsH[kb + tig][r0 + 8];
                afH[mt][2] = AsH[kb + tig + 4][r0];
                afH[mt][3] = AsH[kb + tig + 4][r0 + 8];
                afL[mt][0] = AsL[kb + tig][r0];
                afL[mt][1] = AsL[kb + tig][r0 + 8];
                afL[mt][2] = AsL[kb + tig + 4][r0];
                afL[mt][3] = AsL[kb + tig + 4][r0 + 8];
            }
#pragma unroll
            for (int nt = 0; nt < 4; nt++) {
                const int c0 = wn + nt * 8 + gid;
                bfH[nt][0] = BsH[kb + tig][c0];
                bfH[nt][1] = BsH[kb + tig + 4][c0];
                bfL[nt][0] = BsL[kb + tig][c0];
                bfL[nt][1] = BsL[kb + tig + 4][c0];
            }
#pragma unroll
            for (int mt = 0; mt < 2; mt++)
#pragma unroll
                for (int nt = 0; nt < 4; nt++) {
                    MMA_BF16(acc[mt][nt],
                             afL[mt][0], afL[mt][1], afL[mt][2], afL[mt][3],
                             bfH[nt][0], bfH[nt][1]);
                    MMA_BF16(acc[mt][nt],
                             afH[mt][0], afH[mt][1], afH[mt][2], afH[mt][3],
                             bfL[nt][0], bfL[nt][1]);
                    MMA_BF16(acc[mt][nt],
                             afH[mt][0], afH[mt][1], afH[mt][2], afH[mt][3],
                             bfH[nt][0], bfH[nt][1]);
                }
        }
    }

#pragma unroll
    for (int mt = 0; mt < 2; mt++) {
#pragma unroll
        for (int nt = 0; nt < 4; nt++) {
            const int m0 = bm + wm + mt * 16 + gid;
            const int n0 = bn + wn + nt * 8 + 2 * tig;
#pragma unroll
            for (int h = 0; h < 2; h++) {
                const int m = m0 + h * 8;
#pragma unroll
                for (int q = 0; q < 2; q++) {
                    const int n = n0 + q;
                    if (n < N) {
                        float v = acc[mt][nt][h * 2 + q] + bias[n];
                        if (res) v += res[(size_t)m * res_ld + n];
                        C[(size_t)m * ldc + n] = v;
                    }
                }
            }
        }
    }
}

// ---------------------------------------------------------------------------
// GRU combine: h_new = (1-z)*n + z*h ; also writes bf16 hi/lo split of h_new
//   gi row index = b * gi_rstride + gi_roff  (batched encoder gi1 support)
// ---------------------------------------------------------------------------
__global__ void gru_combine_kernel(long long gi_off, int gi_rstride, int gi_roff,
                                   long long gh_off, long long h_off, long long hb)
{
    const int idx = blockIdx.x * blockDim.x + threadIdx.x;
    if (idx >= BQ * RQ) return;
    const int b = idx >> 10;
    const int j = idx & (RQ - 1);

    const float* gi = g_scratch + gi_off;
    const float* gh = g_scratch + gh_off;
    float*       h  = g_scratch + h_off;

    const size_t gr = ((size_t)b * gi_rstride + gi_roff) * (3 * RQ) + j;
    const float ir = gi[gr], iz = gi[gr + RQ], inn = gi[gr + 2 * RQ];
    const size_t g = (size_t)b * 3 * RQ + j;
    const float hr = gh[g], hz = gh[g + RQ], hn  = gh[g + 2 * RQ];

    const float r = 1.0f / (1.0f + expf(-(ir + hr)));
    const float z = 1.0f / (1.0f + expf(-(iz + hz)));
    const float n = tanhf(inn + r * hn);

    const size_t hi = (size_t)b * 2 * RQ + j;
    const float hp = h[hi];
    const float v = (1.0f - z) * n + z * hp;
    h[hi] = v;

    const __nv_bfloat16 vh = __float2bfloat16(v);
    const size_t bo = (size_t)b * 2 * RQ + hb + j;
    g_bf[OFFB_HH + bo] = vh;
    g_bf[OFFB_HL + bo] = __float2bfloat16(v - __bfloat162float(vh));
}

// ---------------------------------------------------------------------------
// Weight split, decoder input assembly, zero fills
// ---------------------------------------------------------------------------
__global__ void split_w_kernel(const float* __restrict__ W,
                               long long dh, long long dl, int count)
{
    const int i = blockIdx.x * blockDim.x + threadIdx.x;
    if (i >= count) return;
    const float v = W[i];
    const __nv_bfloat16 h = __float2bfloat16(v);
    g_bf[dh + i] = h;
    g_bf[dl + i] = __float2bfloat16(v - __bfloat162float(h));
}

__global__ void build_x_kernel(const float* __restrict__ dec,
                               const float* __restrict__ out, int t)
{
    const int idx = blockIdx.x * blockDim.x + threadIdx.x;
    if (idx >= BQ * IQ) return;
    const int b = idx / IQ;
    const int i = idx - b * IQ;
    float v;
    if (t == 0) {
        v = dec[(size_t)b * TGTQ * IQ + i];
    } else if (i < HQ) {
        v = out[(size_t)(b * TGTQ + (t - 1)) * HQ + i];
    } else {
        v = dec[(size_t)(b * TGTQ + t) * IQ + i];
    }
    g_scratch[OFF_X + idx] = v;
}

__global__ void zero_kernel(long long off, long long count)
{
    const long long idx = (long long)blockIdx.x * blockDim.x + threadIdx.x;
    if (idx < count) g_scratch[off + idx] = 0.0f;
}

__global__ void zero_bf_kernel(long long off, long long count)
{
    const long long idx = (long long)blockIdx.x * blockDim.x + threadIdx.x;
    if (idx < count) g_bf[off + idx] = __float2bfloat16(0.0f);
}

// ---------------------------------------------------------------------------
// Launch
// ---------------------------------------------------------------------------
extern "C" void kernel_launch(void* const* d_in, const int* in_sizes, int n_in,
                              void* d_out, int out_size)
{
    const float* enc = (const float*)d_in[0];
    const float* dec = (const float*)d_in[1];
    const float* Wi1 = (const float*)d_in[2];
    const float* Wh1 = (const float*)d_in[3];
    const float* bi1 = (const float*)d_in[4];
    const float* bh1 = (const float*)d_in[5];
    const float* Wi2 = (const float*)d_in[6];
    const float* Wh2 = (const float*)d_in[7];
    const float* bi2 = (const float*)d_in[8];
    const float* bh2 = (const float*)d_in[9];
    const float* Wfc = (const float*)d_in[10];
    const float* bfc = (const float*)d_in[11];
    float* out = (float*)d_out;
    (void)in_sizes; (void)n_in; (void)out_size;

    const dim3 blk(256);
    const dim3 gridBig1(GLDC / 128, BQ / 128, 1);          // (24, 32, 1)
    const dim3 gridBig2(GLDC / 128, BQ / 128, 2);          // (24, 32, 2) fused
    const dim3 grid3R((3 * RQ) / BN, BQ / BM);             // (48, 32)
    const dim3 gridEnc((3 * RQ) / BN, (BQ * SRCM1) / BM);  // (48, 1568) batched gi1
    const dim3 gridFC((HQ + BN - 1) / BN, BQ / BM);        // (2, 32)
    const int  combine_blocks = (BQ * RQ) / 256;
    const int  bx_blocks = (BQ * IQ + 255) / 256;
    const int  wsplit_blocks = (int)((NW + 255) / 256);

    // per-launch init: zero h (fp32 + splits), split weights
    zero_kernel<<<(int)((BQ * 2LL * RQ + 255) / 256), blk>>>(OFF_HCAT, (long long)BQ * 2 * RQ);
    zero_bf_kernel<<<(int)((2LL * BQ * 2 * RQ + 255) / 256), blk>>>(OFFB_HH, 2LL * BQ * 2 * RQ);
    split_w_kernel<<<wsplit_blocks, blk>>>(Wh1, OFFB_W1H, OFFB_W1L, (int)NW);
    split_w_kernel<<<wsplit_blocks, blk>>>(Wi2, OFFB_W2H, OFFB_W2L, (int)NW);
    split_w_kernel<<<wsplit_blocks, blk>>>(Wh2, OFFB_W3H, OFFB_W3L, (int)NW);

    // batched encoder gi1: enc flattened is row-major [BQ*49, IQ], row m = b*49+t
    gemm_bf16x3_kernel<<<gridEnc, blk>>>(enc, -1, IQ,
                                         Wi1, bi1, -1, 0,
                                         nullptr, OFF_GIALL, 3 * RQ, 3 * RQ, IQ);

    // ---------------- encoder: 49 steps ----------------
    for (int t = 0; t < SRCM1; t++) {
        gemm_big_kernel<<<gridBig1, blk>>>(OFFB_HH, OFFB_HL, OFFB_W1H, OFFB_W1L,
                                           bh1, OFF_GH1,
                                           OFFB_HH, OFFB_HL, OFFB_W1H, OFFB_W1L,
                                           bh1, OFF_GH1);
        gru_combine_kernel<<<combine_blocks, blk>>>(OFF_GIALL, SRCM1, t,
                                                    OFF_GH1, OFF_HCAT, 0);

        gemm_big_kernel<<<gridBig2, blk>>>(OFFB_HH, OFFB_HL, OFFB_W2H, OFFB_W2L,
                                           bi2, OFF_GI2,
                                           OFFB_HH + RQ, OFFB_HL + RQ, OFFB_W3H, OFFB_W3L,
                                           bh2, OFF_GH2);
        gru_combine_kernel<<<combine_blocks, blk>>>(OFF_GI2, 1, 0,
                                                    OFF_GH2, OFF_HCAT + RQ, RQ);
    }

    // ---------------- decoder: 25 steps ----------------
    for (int t = 0; t < TGTQ; t++) {
        build_x_kernel<<<bx_blocks, blk>>>(dec, out, t);

        gemm_bf16x3_kernel<<<grid3R, blk>>>(nullptr, OFF_X, IQ,
                                            Wi1, bi1, -1, 0,
                                            nullptr, OFF_GI1, 3 * RQ, 3 * RQ, IQ);
        gemm_big_kernel<<<gridBig1, blk>>>(OFFB_HH, OFFB_HL, OFFB_W1H, OFFB_W1L,
                                           bh1, OFF_GH1,
                                           OFFB_HH, OFFB_HL, OFFB_W1H, OFFB_W1L,
                                           bh1, OFF_GH1);
        gru_combine_kernel<<<combine_blocks, blk>>>(OFF_GI1, 1, 0,
                                                    OFF_GH1, OFF_HCAT, 0);

        gemm_big_kernel<<<gridBig2, blk>>>(OFFB_HH, OFFB_HL, OFFB_W2H, OFFB_W2L,
                                           bi2, OFF_GI2,
                                           OFFB_HH + RQ, OFFB_HL + RQ, OFFB_W3H, OFFB_W3L,
                                           bh2, OFF_GH2);
        gru_combine_kernel<<<combine_blocks, blk>>>(OFF_GI2, 1, 0,
                                                    OFF_GH2, OFF_HCAT + RQ, RQ);

        gemm_bf16x3_kernel<<<gridFC, blk>>>(nullptr, OFF_HCAT, 2 * RQ,
                                            Wfc, bfc, OFF_X, IQ,
                                            out + (size_t)t * HQ, -1, TGTQ * HQ,
                                            HQ, 2 * RQ);
    }
}